// round 10
// baseline (speedup 1.0000x reference)
#include <cuda_runtime.h>

#define HH   4
#define FF   32
#define HFD  128          // H*F
#define FIN  128
#define EDIM 64
#define HID  256
#define BB   64
#define MLE  1500
#define NN   (BB*MLE)     // 96000
#define EE   600000
#define CAP  64           // per-node incidence capacity (P(overflow) ~ 1e-50)

typedef unsigned long long u64;

// ---------------- scratch (device globals; no allocation allowed) ----------
__device__ float g_proj[NN*HFD];      // 49.2 MB
__device__ float g_ss[NN*HH];
__device__ float g_st[NN*HH];
__device__ float g_s[EE*HH];          // RAW scores (exp applied in gather)
__device__ float g_usrc[BB*HFD];
__device__ float g_utrg[BB*HFD];
__device__ float g_v[BB*HH*EDIM];
__device__ unsigned g_max_ord;
__device__ int g_degt[NN];
__device__ int g_degs[NN];
__device__ int g_listt[NN*CAP];       // edge ids whose trg == n
__device__ int g_lists[NN*CAP];       // edge ids whose src == n

// ---------------- helpers --------------------------------------------------
__device__ __forceinline__ unsigned f2ord(float f) {
    unsigned b = __float_as_uint(f);
    return (b & 0x80000000u) ? ~b : (b | 0x80000000u);
}
__device__ __forceinline__ float ord2f(unsigned u) {
    unsigned b = (u & 0x80000000u) ? (u & 0x7fffffffu) : ~u;
    return __uint_as_float(b);
}
__device__ __forceinline__ float lrelu(float x) { return x > 0.f ? x : 0.2f * x; }
__device__ __forceinline__ float comp4(float4 v, int h) {
    return h == 0 ? v.x : h == 1 ? v.y : h == 2 ? v.z : v.w;
}
// packed f32x2 (sm_103a FFMA2 — only reachable via PTX)
__device__ __forceinline__ u64 pack2(float lo, float hi) {
    u64 r; asm("mov.b64 %0, {%1, %2};" : "=l"(r) : "f"(lo), "f"(hi)); return r;
}
__device__ __forceinline__ void unpack2(u64 v, float& lo, float& hi) {
    asm("mov.b64 {%0, %1}, %2;" : "=f"(lo), "=f"(hi) : "l"(v));
}
__device__ __forceinline__ u64 fma2(u64 a, u64 b, u64 c) {
    u64 d; asm("fma.rn.f32x2 %0, %1, %2, %3;" : "=l"(d) : "l"(a), "l"(b), "l"(c)); return d;
}

// ---------------- K0: zero degree counters + init max ----------------------
__global__ void zero_kernel() {
    int i = blockIdx.x * 256 + threadIdx.x;
    if (i < NN / 4) {
        ((int4*)g_degt)[i] = make_int4(0, 0, 0, 0);
        ((int4*)g_degs)[i] = make_int4(0, 0, 0, 0);
    }
    if (i == 0) g_max_ord = 0x007FFFFFu;   // encodes -inf
}

// ---------------- K1: per-batch instruction bridges ------------------------
__global__ void prep_kernel(const float* __restrict__ ins,
                            const float* __restrict__ Wsi, const float* __restrict__ bsi,
                            const float* __restrict__ Wti, const float* __restrict__ bti,
                            const float* __restrict__ Wei, const float* __restrict__ bei,
                            const float* __restrict__ asrc, const float* __restrict__ atrg,
                            const float* __restrict__ aedge, const float* __restrict__ Wedge) {
    __shared__ float si[HID];
    __shared__ float ce[HFD];
    int b = blockIdx.x, t = threadIdx.x;   // 128 threads
    for (int k = t; k < HID; k += 128) si[k] = ins[b * HID + k];
    __syncthreads();
    float s1 = bsi[t], s2 = bti[t], s3 = bei[t];
    for (int k = 0; k < HID; k++) {
        float iv = si[k];
        s1 += iv * Wsi[k * HFD + t];
        s2 += iv * Wti[k * HFD + t];
        s3 += iv * Wei[k * HFD + t];
    }
    g_usrc[b * HFD + t] = s1 * asrc[t];
    g_utrg[b * HFD + t] = s2 * atrg[t];
    ce[t] = s3 * aedge[t];
    __syncthreads();
    for (int o = t; o < HH * EDIM; o += 128) {
        int h = o >> 6, d = o & 63;
        float v = 0.f;
        #pragma unroll
        for (int f = 0; f < FF; f++) v += Wedge[d * HFD + h * FF + f] * ce[h * FF + f];
        g_v[b * HH * EDIM + o] = v;
    }
}

// ---------------- K2: fused node GEMM (FFMA2) + scores + skip init ---------
#define TILE_N 64
#define KCOLS  256
#define XPAD   132
#define SMEM_BYTES ((FIN*KCOLS + TILE_N*XPAD) * 4)

__global__ void node_kernel(const float* __restrict__ x,
                            const float* __restrict__ Wp,
                            const float* __restrict__ Wsk,
                            const float* __restrict__ bias,
                            float* __restrict__ out) {
    extern __shared__ float smem[];
    float* sW = smem;                 // [128][256]
    float* sX = smem + FIN * KCOLS;   // [64][132] padded (reused as proj tile)
    int tid = threadIdx.x;

    const float4* Wp4 = (const float4*)Wp;
    const float4* Ws4 = (const float4*)Wsk;
    for (int i4 = tid; i4 < FIN * KCOLS / 4; i4 += 256) {
        int k = i4 >> 6, c4 = i4 & 63;
        float4 v = (c4 < 32) ? Wp4[k * 32 + c4] : Ws4[k * 32 + (c4 - 32)];
        ((float4*)sW)[i4] = v;
    }
    int base = blockIdx.x * TILE_N;
    const float4* x4 = (const float4*)x;
    for (int i = tid; i < TILE_N * 32; i += 256) {
        int r = i >> 5, k4 = i & 31;
        float4 v = x4[(base + r) * 32 + k4];
        *(float4*)&sX[r * XPAD + k4 * 4] = v;
    }
    __syncthreads();

    int tcol = tid & 31, trow = tid >> 5;
    u64 acc2[8][4];
    #pragma unroll
    for (int j = 0; j < 8; j++)
        #pragma unroll
        for (int i = 0; i < 4; i++) acc2[j][i] = 0ull;

    for (int kk = 0; kk < FIN; kk += 4) {
        float4 xv4[8];
        #pragma unroll
        for (int j = 0; j < 8; j++)
            xv4[j] = *(const float4*)&sX[(trow * 8 + j) * XPAD + kk];  // broadcast
        #pragma unroll
        for (int q = 0; q < 4; q++) {
            int k = kk + q;
            u64 wr2[4];
            #pragma unroll
            for (int i = 0; i < 4; i++)
                wr2[i] = *(const u64*)&sW[k * KCOLS + 2 * (tcol + 32 * i)];
            #pragma unroll
            for (int j = 0; j < 8; j++) {
                float xv = (q == 0) ? xv4[j].x : (q == 1) ? xv4[j].y
                          : (q == 2) ? xv4[j].z : xv4[j].w;
                u64 x2 = pack2(xv, xv);
                #pragma unroll
                for (int i = 0; i < 4; i++) acc2[j][i] = fma2(x2, wr2[i], acc2[j][i]);
            }
        }
    }
    __syncthreads();

    #pragma unroll
    for (int j = 0; j < 8; j++) {
        int ln = trow * 8 + j;
        int gn = base + ln;
        #pragma unroll
        for (int i = 0; i < 4; i++) {
            int c0 = 2 * (tcol + 32 * i);
            float lo, hi; unpack2(acc2[j][i], lo, hi);
            if (i < 2) {
                *(float2*)&g_proj[gn * HFD + c0] = make_float2(lo, hi);
                sX[ln * XPAD + c0] = lo;
                sX[ln * XPAD + c0 + 1] = hi;
            } else {
                int oj = c0 - HFD;
                float o0 = lo + bias[oj];
                float o1 = hi + bias[oj + 1];
                out[(size_t)gn * 256 + oj] = o0;
                out[(size_t)gn * 256 + oj + 1] = o1;
                out[(size_t)gn * 256 + 128 + oj] = o0;
                out[(size_t)gn * 256 + 128 + oj + 1] = o1;
            }
        }
    }
    __syncthreads();

    int ln = tid & 63, h = tid >> 6;
    int gn = base + ln;
    int b = gn / MLE;
    const float* us = g_usrc + b * HFD + h * FF;
    const float* ut = g_utrg + b * HFD + h * FF;
    const float* pr = sX + ln * XPAD + h * FF;
    float a = 0.f, c2 = 0.f;
    #pragma unroll
    for (int f = 0; f < FF; f++) { float p = pr[f]; a = fmaf(p, us[f], a); c2 = fmaf(p, ut[f], c2); }
    g_ss[gn * HH + h] = a;
    g_st[gn * HH + h] = c2;
}

// ---------------- K3: per-edge scores + incidence lists --------------------
#define SV_F4 (BB*65)
#define ESC_SMEM (SV_F4*16)

__global__ void escore_kernel(const int* __restrict__ eidx,
                              const float* __restrict__ edges,
                              const int* __restrict__ bids) {
    extern __shared__ float4 sv[];
    const float4* v4 = (const float4*)g_v;
    for (int i = threadIdx.x; i < BB * 64; i += 256) {
        int b = i >> 6, r = i & 63;
        sv[b * 65 + r] = v4[i];
    }
    __syncthreads();

    float m = -3.4e38f;
    for (int e = blockIdx.x * 256 + threadIdx.x; e < EE; e += gridDim.x * 256) {
        int b = bids[e];
        int src = eidx[e], trg = eidx[EE + e];
        const float4* er = (const float4*)edges + e * 16;
        const float4* vb = sv + b * 65;
        float se0 = 0.f, se1 = 0.f, se2 = 0.f, se3 = 0.f;
        #pragma unroll
        for (int q = 0; q < 16; q++) {
            float4 ev = er[q];
            float4 v0 = vb[q], v1 = vb[16 + q], v2 = vb[32 + q], v3 = vb[48 + q];
            se0 += ev.x * v0.x + ev.y * v0.y + ev.z * v0.z + ev.w * v0.w;
            se1 += ev.x * v1.x + ev.y * v1.y + ev.z * v1.z + ev.w * v1.w;
            se2 += ev.x * v2.x + ev.y * v2.y + ev.z * v2.z + ev.w * v2.w;
            se3 += ev.x * v3.x + ev.y * v3.y + ev.z * v3.z + ev.w * v3.w;
        }
        float4 ss = ((const float4*)g_ss)[src];
        float4 st = ((const float4*)g_st)[trg];
        float s0 = lrelu(ss.x + st.x + se0);
        float s1 = lrelu(ss.y + st.y + se1);
        float s2 = lrelu(ss.z + st.z + se2);
        float s3 = lrelu(ss.w + st.w + se3);
        ((float4*)g_s)[e] = make_float4(s0, s1, s2, s3);   // raw scores
        m = fmaxf(m, fmaxf(fmaxf(s0, s1), fmaxf(s2, s3)));
        // incidence lists (LTS atomics overlap the L1-bound dot product)
        int pt = atomicAdd(&g_degt[trg], 1);
        if (pt < CAP) g_listt[trg * CAP + pt] = e;
        int ps = atomicAdd(&g_degs[src], 1);
        if (ps < CAP) g_lists[src * CAP + ps] = e;
    }
    #pragma unroll
    for (int off = 16; off; off >>= 1) m = fmaxf(m, __shfl_xor_sync(0xffffffffu, m, off));
    __shared__ float wm[8];
    if ((threadIdx.x & 31) == 0) wm[threadIdx.x >> 5] = m;
    __syncthreads();
    if (threadIdx.x < 8) {
        m = wm[threadIdx.x];
        #pragma unroll
        for (int off = 4; off; off >>= 1) m = fmaxf(m, __shfl_xor_sync(0xffu, m, off));
        if (threadIdx.x == 0) atomicMax(&g_max_ord, f2ord(m));
    }
}

// ---------------- K4: gather: exp + denom + aggregate + skip + LayerNorm ---
// warp per node. Raw scores exp'd on staging; denominators accumulated in the
// same loop as the aggregation (division is linear: sum(p*e)/D == sum(p*e/D)).
__global__ void gather_kernel(const int* __restrict__ eidx,
                              const float* __restrict__ gamma,
                              const float* __restrict__ beta,
                              float* __restrict__ out) {
    __shared__ int   s_nbr[2][8][32];
    __shared__ float s_ex [2][8][32][4];
    int w = threadIdx.x >> 5;
    int n = blockIdx.x * 8 + w;
    int lane = threadIdx.x & 31;
    int h = lane >> 3;
    float M = ord2f(g_max_ord);
    int dt = g_degt[n]; if (dt > CAP) dt = CAP;
    int ds = g_degs[n]; if (ds > CAP) ds = CAP;
    int m32t = dt < 32 ? dt : 32;
    int m32s = ds < 32 ? ds : 32;
    const float4* sc4 = (const float4*)g_s;
    const float4* pr4 = (const float4*)g_proj;

    if (lane < m32t) {
        int e = g_listt[n * CAP + lane];
        s_nbr[0][w][lane] = __ldg(eidx + e);
        float4 sc = __ldg(sc4 + e);
        s_ex[0][w][lane][0] = __expf(sc.x - M);
        s_ex[0][w][lane][1] = __expf(sc.y - M);
        s_ex[0][w][lane][2] = __expf(sc.z - M);
        s_ex[0][w][lane][3] = __expf(sc.w - M);
    }
    if (lane < m32s) {
        int e = g_lists[n * CAP + lane];
        s_nbr[1][w][lane] = __ldg(eidx + EE + e);
        float4 sc = __ldg(sc4 + e);
        s_ex[1][w][lane][0] = __expf(sc.x - M);
        s_ex[1][w][lane][1] = __expf(sc.y - M);
        s_ex[1][w][lane][2] = __expf(sc.z - M);
        s_ex[1][w][lane][3] = __expf(sc.w - M);
    }
    __syncwarp();

    float dT = 0.f, dS = 0.f;
    float4 aT = make_float4(0.f, 0.f, 0.f, 0.f);
    float4 aS = make_float4(0.f, 0.f, 0.f, 0.f);
    int mmax = m32t > m32s ? m32t : m32s;
    for (int it = 0; it < mmax; it += 4) {
        #pragma unroll
        for (int j = 0; j < 4; j++) {
            int idx = it + j;
            if (idx < m32t) {
                int nbr = s_nbr[0][w][idx];           // broadcast LDS
                float a = s_ex[0][w][idx][h];         // 4-way broadcast LDS
                float4 p = __ldg(pr4 + nbr * 32 + lane);
                dT += a;
                aT.x += p.x * a; aT.y += p.y * a; aT.z += p.z * a; aT.w += p.w * a;
            }
            if (idx < m32s) {
                int nbr = s_nbr[1][w][idx];
                float a = s_ex[1][w][idx][h];
                float4 p = __ldg(pr4 + nbr * 32 + lane);
                dS += a;
                aS.x += p.x * a; aS.y += p.y * a; aS.z += p.z * a; aS.w += p.w * a;
            }
        }
    }
    // rare tails (deg > 32)
    for (int it = 32; it < dt; it++) {
        int e = g_listt[n * CAP + it];
        float a = __expf(comp4(sc4[e], h) - M);
        int nbr = eidx[e];
        float4 p = pr4[nbr * 32 + lane];
        dT += a;
        aT.x += p.x * a; aT.y += p.y * a; aT.z += p.z * a; aT.w += p.w * a;
    }
    for (int it = 32; it < ds; it++) {
        int e = g_lists[n * CAP + it];
        float a = __expf(comp4(sc4[e], h) - M);
        int nbr = eidx[EE + e];
        float4 p = pr4[nbr * 32 + lane];
        dS += a;
        aS.x += p.x * a; aS.y += p.y * a; aS.z += p.z * a; aS.w += p.w * a;
    }

    float rT = 1.f / (dT + 1e-16f);
    float rS = 1.f / (dS + 1e-16f);

    float4* row = (float4*)(out + (size_t)n * 256);
    float4 v1 = row[lane];        // skip+bias (src half)
    float4 v2 = row[32 + lane];   // skip+bias (trg half)
    v1.x += aS.x * rS; v1.y += aS.y * rS; v1.z += aS.z * rS; v1.w += aS.w * rS;
    v2.x += aT.x * rT; v2.y += aT.y * rT; v2.z += aT.z * rT; v2.w += aT.w * rT;

    // LayerNorm over 256 within the warp
    float s = v1.x + v1.y + v1.z + v1.w + v2.x + v2.y + v2.z + v2.w;
    #pragma unroll
    for (int off = 16; off; off >>= 1) s += __shfl_xor_sync(0xffffffffu, s, off);
    float mu = s * (1.f / 256.f);
    float dx, sq = 0.f;
    dx = v1.x - mu; sq += dx * dx;  dx = v1.y - mu; sq += dx * dx;
    dx = v1.z - mu; sq += dx * dx;  dx = v1.w - mu; sq += dx * dx;
    dx = v2.x - mu; sq += dx * dx;  dx = v2.y - mu; sq += dx * dx;
    dx = v2.z - mu; sq += dx * dx;  dx = v2.w - mu; sq += dx * dx;
    #pragma unroll
    for (int off = 16; off; off >>= 1) sq += __shfl_xor_sync(0xffffffffu, sq, off);
    float inv = rsqrtf(sq * (1.f / 256.f) + 1e-5f);
    float4 g1 = ((const float4*)gamma)[lane], g2 = ((const float4*)gamma)[32 + lane];
    float4 b1 = ((const float4*)beta)[lane],  b2 = ((const float4*)beta)[32 + lane];
    v1.x = (v1.x - mu) * inv * g1.x + b1.x;  v1.y = (v1.y - mu) * inv * g1.y + b1.y;
    v1.z = (v1.z - mu) * inv * g1.z + b1.z;  v1.w = (v1.w - mu) * inv * g1.w + b1.w;
    v2.x = (v2.x - mu) * inv * g2.x + b2.x;  v2.y = (v2.y - mu) * inv * g2.y + b2.y;
    v2.z = (v2.z - mu) * inv * g2.z + b2.z;  v2.w = (v2.w - mu) * inv * g2.w + b2.w;
    row[lane] = v1;
    row[32 + lane] = v2;
}

// ---------------- launch ---------------------------------------------------
extern "C" void kernel_launch(void* const* d_in, const int* in_sizes, int n_in,
                              void* d_out, int out_size) {
    int o = (in_sizes[5] == 1) ? 0 : -1;
    const float* x     = (const float*)d_in[0];
    const int*   eidx  = (const int*)  d_in[1];
    const float* edges = (const float*)d_in[2];
    const float* ins   = (const float*)d_in[3];
    const int*   bids  = (const int*)  d_in[4];
    const float* Wp    = (const float*)d_in[6 + o];
    const float* We    = (const float*)d_in[7 + o];
    const float* Wsi   = (const float*)d_in[8 + o];
    const float* bsi   = (const float*)d_in[9 + o];
    const float* Wti   = (const float*)d_in[10 + o];
    const float* bti   = (const float*)d_in[11 + o];
    const float* Wei   = (const float*)d_in[12 + o];
    const float* bei   = (const float*)d_in[13 + o];
    const float* asrc  = (const float*)d_in[14 + o];
    const float* atrg  = (const float*)d_in[15 + o];
    const float* aedge = (const float*)d_in[16 + o];
    const float* bias  = (const float*)d_in[17 + o];
    const float* Wsk   = (const float*)d_in[18 + o];
    const float* gam   = (const float*)d_in[19 + o];
    const float* bet   = (const float*)d_in[20 + o];
    float* out = (float*)d_out;

    cudaFuncSetAttribute(node_kernel, cudaFuncAttributeMaxDynamicSharedMemorySize, SMEM_BYTES);
    cudaFuncSetAttribute(escore_kernel, cudaFuncAttributeMaxDynamicSharedMemorySize, ESC_SMEM);

    zero_kernel<<<(NN / 4 + 255) / 256, 256>>>();
    prep_kernel<<<BB, 128>>>(ins, Wsi, bsi, Wti, bti, Wei, bei, asrc, atrg, aedge, We);
    node_kernel<<<NN / TILE_N, 256, SMEM_BYTES>>>(x, Wp, Wsk, bias, out);
    escore_kernel<<<444, 256, ESC_SMEM>>>(eidx, edges, bids);
    gather_kernel<<<NN / 8, 256>>>(eidx, gam, bet, out);
}

// round 11
// speedup vs baseline: 1.0411x; 1.0411x over previous
#include <cuda_runtime.h>

#define HH   4
#define FF   32
#define HFD  128          // H*F
#define FIN  128
#define EDIM 64
#define HID  256
#define BB   64
#define MLE  1500
#define NN   (BB*MLE)     // 96000
#define EE   600000
#define CAP  64           // per-node incidence capacity (P(overflow) ~ 1e-50)

typedef unsigned long long u64;

// ---------------- scratch (device globals; no allocation allowed) ----------
__device__ float g_proj[NN*HFD];      // 49.2 MB
__device__ float g_ss[NN*HH];
__device__ float g_st[NN*HH];
__device__ float g_s[EE*HH];          // RAW scores (exp applied in gather)
__device__ float g_usrc[BB*HFD];
__device__ float g_utrg[BB*HFD];
__device__ float g_v[BB*HH*EDIM];
__device__ unsigned g_max_ord;
__device__ int g_degt[NN];
__device__ int g_degs[NN];
__device__ int g_listt[NN*CAP];       // edge ids whose trg == n
__device__ int g_lists[NN*CAP];       // edge ids whose src == n

// ---------------- helpers --------------------------------------------------
__device__ __forceinline__ unsigned f2ord(float f) {
    unsigned b = __float_as_uint(f);
    return (b & 0x80000000u) ? ~b : (b | 0x80000000u);
}
__device__ __forceinline__ float ord2f(unsigned u) {
    unsigned b = (u & 0x80000000u) ? (u & 0x7fffffffu) : ~u;
    return __uint_as_float(b);
}
__device__ __forceinline__ float lrelu(float x) { return x > 0.f ? x : 0.2f * x; }
__device__ __forceinline__ float comp4(float4 v, int h) {
    return h == 0 ? v.x : h == 1 ? v.y : h == 2 ? v.z : v.w;
}
// packed f32x2 (sm_103a FFMA2 — only reachable via PTX)
__device__ __forceinline__ u64 pack2(float lo, float hi) {
    u64 r; asm("mov.b64 %0, {%1, %2};" : "=l"(r) : "f"(lo), "f"(hi)); return r;
}
__device__ __forceinline__ void unpack2(u64 v, float& lo, float& hi) {
    asm("mov.b64 {%0, %1}, %2;" : "=f"(lo), "=f"(hi) : "l"(v));
}
__device__ __forceinline__ u64 fma2(u64 a, u64 b, u64 c) {
    u64 d; asm("fma.rn.f32x2 %0, %1, %2, %3;" : "=l"(d) : "l"(a), "l"(b), "l"(c)); return d;
}

// ---------------- K0: zero degree counters + init max ----------------------
__global__ void zero_kernel() {
    int i = blockIdx.x * 256 + threadIdx.x;
    if (i < NN / 4) {
        ((int4*)g_degt)[i] = make_int4(0, 0, 0, 0);
        ((int4*)g_degs)[i] = make_int4(0, 0, 0, 0);
    }
    if (i == 0) g_max_ord = 0x007FFFFFu;   // encodes -inf
}

// ---------------- K1: per-batch instruction bridges ------------------------
__global__ void prep_kernel(const float* __restrict__ ins,
                            const float* __restrict__ Wsi, const float* __restrict__ bsi,
                            const float* __restrict__ Wti, const float* __restrict__ bti,
                            const float* __restrict__ Wei, const float* __restrict__ bei,
                            const float* __restrict__ asrc, const float* __restrict__ atrg,
                            const float* __restrict__ aedge, const float* __restrict__ Wedge) {
    __shared__ float si[HID];
    __shared__ float ce[HFD];
    int b = blockIdx.x, t = threadIdx.x;   // 128 threads
    for (int k = t; k < HID; k += 128) si[k] = ins[b * HID + k];
    __syncthreads();
    float s1 = bsi[t], s2 = bti[t], s3 = bei[t];
    for (int k = 0; k < HID; k++) {
        float iv = si[k];
        s1 += iv * Wsi[k * HFD + t];
        s2 += iv * Wti[k * HFD + t];
        s3 += iv * Wei[k * HFD + t];
    }
    g_usrc[b * HFD + t] = s1 * asrc[t];
    g_utrg[b * HFD + t] = s2 * atrg[t];
    ce[t] = s3 * aedge[t];
    __syncthreads();
    for (int o = t; o < HH * EDIM; o += 128) {
        int h = o >> 6, d = o & 63;
        float v = 0.f;
        #pragma unroll
        for (int f = 0; f < FF; f++) v += Wedge[d * HFD + h * FF + f] * ce[h * FF + f];
        g_v[b * HH * EDIM + o] = v;
    }
}

// ---------------- K2: fused node GEMM (FFMA2) + scores + skip init ---------
#define TILE_N 64
#define KCOLS  256
#define XPAD   132
#define SMEM_BYTES ((FIN*KCOLS + TILE_N*XPAD) * 4)

__global__ void node_kernel(const float* __restrict__ x,
                            const float* __restrict__ Wp,
                            const float* __restrict__ Wsk,
                            const float* __restrict__ bias,
                            float* __restrict__ out) {
    extern __shared__ float smem[];
    float* sW = smem;                 // [128][256]
    float* sX = smem + FIN * KCOLS;   // [64][132] padded (reused as proj tile)
    int tid = threadIdx.x;

    const float4* Wp4 = (const float4*)Wp;
    const float4* Ws4 = (const float4*)Wsk;
    for (int i4 = tid; i4 < FIN * KCOLS / 4; i4 += 256) {
        int k = i4 >> 6, c4 = i4 & 63;
        float4 v = (c4 < 32) ? Wp4[k * 32 + c4] : Ws4[k * 32 + (c4 - 32)];
        ((float4*)sW)[i4] = v;
    }
    int base = blockIdx.x * TILE_N;
    const float4* x4 = (const float4*)x;
    for (int i = tid; i < TILE_N * 32; i += 256) {
        int r = i >> 5, k4 = i & 31;
        float4 v = x4[(base + r) * 32 + k4];
        *(float4*)&sX[r * XPAD + k4 * 4] = v;
    }
    __syncthreads();

    int tcol = tid & 31, trow = tid >> 5;
    u64 acc2[8][4];
    #pragma unroll
    for (int j = 0; j < 8; j++)
        #pragma unroll
        for (int i = 0; i < 4; i++) acc2[j][i] = 0ull;

    for (int kk = 0; kk < FIN; kk += 4) {
        float4 xv4[8];
        #pragma unroll
        for (int j = 0; j < 8; j++)
            xv4[j] = *(const float4*)&sX[(trow * 8 + j) * XPAD + kk];  // broadcast
        #pragma unroll
        for (int q = 0; q < 4; q++) {
            int k = kk + q;
            u64 wr2[4];
            #pragma unroll
            for (int i = 0; i < 4; i++)
                wr2[i] = *(const u64*)&sW[k * KCOLS + 2 * (tcol + 32 * i)];
            #pragma unroll
            for (int j = 0; j < 8; j++) {
                float xv = (q == 0) ? xv4[j].x : (q == 1) ? xv4[j].y
                          : (q == 2) ? xv4[j].z : xv4[j].w;
                u64 x2 = pack2(xv, xv);
                #pragma unroll
                for (int i = 0; i < 4; i++) acc2[j][i] = fma2(x2, wr2[i], acc2[j][i]);
            }
        }
    }
    __syncthreads();

    #pragma unroll
    for (int j = 0; j < 8; j++) {
        int ln = trow * 8 + j;
        int gn = base + ln;
        #pragma unroll
        for (int i = 0; i < 4; i++) {
            int c0 = 2 * (tcol + 32 * i);
            float lo, hi; unpack2(acc2[j][i], lo, hi);
            if (i < 2) {
                *(float2*)&g_proj[gn * HFD + c0] = make_float2(lo, hi);
                sX[ln * XPAD + c0] = lo;
                sX[ln * XPAD + c0 + 1] = hi;
            } else {
                int oj = c0 - HFD;
                float o0 = lo + bias[oj];
                float o1 = hi + bias[oj + 1];
                out[(size_t)gn * 256 + oj] = o0;
                out[(size_t)gn * 256 + oj + 1] = o1;
                out[(size_t)gn * 256 + 128 + oj] = o0;
                out[(size_t)gn * 256 + 128 + oj + 1] = o1;
            }
        }
    }
    __syncthreads();

    int ln = tid & 63, h = tid >> 6;
    int gn = base + ln;
    int b = gn / MLE;
    const float* us = g_usrc + b * HFD + h * FF;
    const float* ut = g_utrg + b * HFD + h * FF;
    const float* pr = sX + ln * XPAD + h * FF;
    float a = 0.f, c2 = 0.f;
    #pragma unroll
    for (int f = 0; f < FF; f++) { float p = pr[f]; a = fmaf(p, us[f], a); c2 = fmaf(p, ut[f], c2); }
    g_ss[gn * HH + h] = a;
    g_st[gn * HH + h] = c2;
}

// ---------------- K3: per-edge scores (8 lanes/edge) + incidence lists -----
// Warp handles 4 edges. Each lane loads 32B of its edge row (coalesced: one
// LDG touches 2 lines/edge instead of 32), partial-dots all 4 heads against
// the SMEM v-table, reduces via shfl within the 8-lane group.
#define SV_F4 (BB*65)
#define ESC_SMEM (SV_F4*16)

__global__ void escore_kernel(const int* __restrict__ eidx,
                              const float* __restrict__ edges,
                              const int* __restrict__ bids) {
    extern __shared__ float4 sv[];
    const float4* v4 = (const float4*)g_v;
    for (int i = threadIdx.x; i < BB * 64; i += 256) {
        int b = i >> 6, r = i & 63;
        sv[b * 65 + r] = v4[i];
    }
    __syncthreads();

    int gwarp = (blockIdx.x * 256 + threadIdx.x) >> 5;
    int nwarps = gridDim.x * 8;
    int lane = threadIdx.x & 31;
    int g = lane >> 3, l = lane & 7;

    float m = -3.4e38f;
    for (int grp = gwarp; grp < EE / 4; grp += nwarps) {
        int e = grp * 4 + g;
        int b = __ldg(bids + e);
        const float4* er = (const float4*)edges + e * 16 + l * 2;
        float4 ev0 = er[0];
        float4 ev1 = er[1];
        const float4* vb = sv + b * 65 + l * 2;
        float se[HH];
        #pragma unroll
        for (int h = 0; h < HH; h++) {
            float4 v0 = vb[h * 16], v1 = vb[h * 16 + 1];
            se[h] = ev0.x * v0.x + ev0.y * v0.y + ev0.z * v0.z + ev0.w * v0.w
                  + ev1.x * v1.x + ev1.y * v1.y + ev1.z * v1.z + ev1.w * v1.w;
        }
        #pragma unroll
        for (int off = 1; off < 8; off <<= 1) {
            se[0] += __shfl_xor_sync(0xffffffffu, se[0], off);
            se[1] += __shfl_xor_sync(0xffffffffu, se[1], off);
            se[2] += __shfl_xor_sync(0xffffffffu, se[2], off);
            se[3] += __shfl_xor_sync(0xffffffffu, se[3], off);
        }
        if (l == 0) {
            int src = __ldg(eidx + e), trg = __ldg(eidx + EE + e);
            float4 ss = __ldg((const float4*)g_ss + src);
            float4 st = __ldg((const float4*)g_st + trg);
            float s0 = lrelu(ss.x + st.x + se[0]);
            float s1 = lrelu(ss.y + st.y + se[1]);
            float s2 = lrelu(ss.z + st.z + se[2]);
            float s3 = lrelu(ss.w + st.w + se[3]);
            ((float4*)g_s)[e] = make_float4(s0, s1, s2, s3);   // raw scores
            m = fmaxf(m, fmaxf(fmaxf(s0, s1), fmaxf(s2, s3)));
            int pt = atomicAdd(&g_degt[trg], 1);
            if (pt < CAP) g_listt[trg * CAP + pt] = e;
            int ps = atomicAdd(&g_degs[src], 1);
            if (ps < CAP) g_lists[src * CAP + ps] = e;
        }
    }
    #pragma unroll
    for (int off = 16; off; off >>= 1) m = fmaxf(m, __shfl_xor_sync(0xffffffffu, m, off));
    __shared__ float wm[8];
    if ((threadIdx.x & 31) == 0) wm[threadIdx.x >> 5] = m;
    __syncthreads();
    if (threadIdx.x < 8) {
        m = wm[threadIdx.x];
        #pragma unroll
        for (int off = 4; off; off >>= 1) m = fmaxf(m, __shfl_xor_sync(0xffu, m, off));
        if (threadIdx.x == 0) atomicMax(&g_max_ord, f2ord(m));
    }
}

// ---------------- K4: gather: exp + denom + aggregate + skip + LayerNorm ---
__global__ void gather_kernel(const int* __restrict__ eidx,
                              const float* __restrict__ gamma,
                              const float* __restrict__ beta,
                              float* __restrict__ out) {
    __shared__ int   s_nbr[2][8][32];
    __shared__ float s_ex [2][8][32][4];
    int w = threadIdx.x >> 5;
    int n = blockIdx.x * 8 + w;
    int lane = threadIdx.x & 31;
    int h = lane >> 3;
    float M = ord2f(g_max_ord);
    int dt = g_degt[n]; if (dt > CAP) dt = CAP;
    int ds = g_degs[n]; if (ds > CAP) ds = CAP;
    int m32t = dt < 32 ? dt : 32;
    int m32s = ds < 32 ? ds : 32;
    const float4* sc4 = (const float4*)g_s;
    const float4* pr4 = (const float4*)g_proj;

    if (lane < m32t) {
        int e = g_listt[n * CAP + lane];
        s_nbr[0][w][lane] = __ldg(eidx + e);
        float4 sc = __ldg(sc4 + e);
        s_ex[0][w][lane][0] = __expf(sc.x - M);
        s_ex[0][w][lane][1] = __expf(sc.y - M);
        s_ex[0][w][lane][2] = __expf(sc.z - M);
        s_ex[0][w][lane][3] = __expf(sc.w - M);
    }
    if (lane < m32s) {
        int e = g_lists[n * CAP + lane];
        s_nbr[1][w][lane] = __ldg(eidx + EE + e);
        float4 sc = __ldg(sc4 + e);
        s_ex[1][w][lane][0] = __expf(sc.x - M);
        s_ex[1][w][lane][1] = __expf(sc.y - M);
        s_ex[1][w][lane][2] = __expf(sc.z - M);
        s_ex[1][w][lane][3] = __expf(sc.w - M);
    }
    __syncwarp();

    float dT = 0.f, dS = 0.f;
    float4 aT = make_float4(0.f, 0.f, 0.f, 0.f);
    float4 aS = make_float4(0.f, 0.f, 0.f, 0.f);
    int mmax = m32t > m32s ? m32t : m32s;
    for (int it = 0; it < mmax; it += 4) {
        #pragma unroll
        for (int j = 0; j < 4; j++) {
            int idx = it + j;
            if (idx < m32t) {
                int nbr = s_nbr[0][w][idx];           // broadcast LDS
                float a = s_ex[0][w][idx][h];         // 4-way broadcast LDS
                float4 p = __ldg(pr4 + nbr * 32 + lane);
                dT += a;
                aT.x += p.x * a; aT.y += p.y * a; aT.z += p.z * a; aT.w += p.w * a;
            }
            if (idx < m32s) {
                int nbr = s_nbr[1][w][idx];
                float a = s_ex[1][w][idx][h];
                float4 p = __ldg(pr4 + nbr * 32 + lane);
                dS += a;
                aS.x += p.x * a; aS.y += p.y * a; aS.z += p.z * a; aS.w += p.w * a;
            }
        }
    }
    // rare tails (deg > 32)
    for (int it = 32; it < dt; it++) {
        int e = g_listt[n * CAP + it];
        float a = __expf(comp4(sc4[e], h) - M);
        int nbr = eidx[e];
        float4 p = pr4[nbr * 32 + lane];
        dT += a;
        aT.x += p.x * a; aT.y += p.y * a; aT.z += p.z * a; aT.w += p.w * a;
    }
    for (int it = 32; it < ds; it++) {
        int e = g_lists[n * CAP + it];
        float a = __expf(comp4(sc4[e], h) - M);
        int nbr = eidx[EE + e];
        float4 p = pr4[nbr * 32 + lane];
        dS += a;
        aS.x += p.x * a; aS.y += p.y * a; aS.z += p.z * a; aS.w += p.w * a;
    }

    float rT = 1.f / (dT + 1e-16f);
    float rS = 1.f / (dS + 1e-16f);

    float4* row = (float4*)(out + (size_t)n * 256);
    float4 v1 = row[lane];        // skip+bias (src half)
    float4 v2 = row[32 + lane];   // skip+bias (trg half)
    v1.x += aS.x * rS; v1.y += aS.y * rS; v1.z += aS.z * rS; v1.w += aS.w * rS;
    v2.x += aT.x * rT; v2.y += aT.y * rT; v2.z += aT.z * rT; v2.w += aT.w * rT;

    // LayerNorm over 256 within the warp
    float s = v1.x + v1.y + v1.z + v1.w + v2.x + v2.y + v2.z + v2.w;
    #pragma unroll
    for (int off = 16; off; off >>= 1) s += __shfl_xor_sync(0xffffffffu, s, off);
    float mu = s * (1.f / 256.f);
    float dx, sq = 0.f;
    dx = v1.x - mu; sq += dx * dx;  dx = v1.y - mu; sq += dx * dx;
    dx = v1.z - mu; sq += dx * dx;  dx = v1.w - mu; sq += dx * dx;
    dx = v2.x - mu; sq += dx * dx;  dx = v2.y - mu; sq += dx * dx;
    dx = v2.z - mu; sq += dx * dx;  dx = v2.w - mu; sq += dx * dx;
    #pragma unroll
    for (int off = 16; off; off >>= 1) sq += __shfl_xor_sync(0xffffffffu, sq, off);
    float inv = rsqrtf(sq * (1.f / 256.f) + 1e-5f);
    float4 g1 = ((const float4*)gamma)[lane], g2 = ((const float4*)gamma)[32 + lane];
    float4 b1 = ((const float4*)beta)[lane],  b2 = ((const float4*)beta)[32 + lane];
    v1.x = (v1.x - mu) * inv * g1.x + b1.x;  v1.y = (v1.y - mu) * inv * g1.y + b1.y;
    v1.z = (v1.z - mu) * inv * g1.z + b1.z;  v1.w = (v1.w - mu) * inv * g1.w + b1.w;
    v2.x = (v2.x - mu) * inv * g2.x + b2.x;  v2.y = (v2.y - mu) * inv * g2.y + b2.y;
    v2.z = (v2.z - mu) * inv * g2.z + b2.z;  v2.w = (v2.w - mu) * inv * g2.w + b2.w;
    row[lane] = v1;
    row[32 + lane] = v2;
}

// ---------------- launch ---------------------------------------------------
extern "C" void kernel_launch(void* const* d_in, const int* in_sizes, int n_in,
                              void* d_out, int out_size) {
    int o = (in_sizes[5] == 1) ? 0 : -1;
    const float* x     = (const float*)d_in[0];
    const int*   eidx  = (const int*)  d_in[1];
    const float* edges = (const float*)d_in[2];
    const float* ins   = (const float*)d_in[3];
    const int*   bids  = (const int*)  d_in[4];
    const float* Wp    = (const float*)d_in[6 + o];
    const float* We    = (const float*)d_in[7 + o];
    const float* Wsi   = (const float*)d_in[8 + o];
    const float* bsi   = (const float*)d_in[9 + o];
    const float* Wti   = (const float*)d_in[10 + o];
    const float* bti   = (const float*)d_in[11 + o];
    const float* Wei   = (const float*)d_in[12 + o];
    const float* bei   = (const float*)d_in[13 + o];
    const float* asrc  = (const float*)d_in[14 + o];
    const float* atrg  = (const float*)d_in[15 + o];
    const float* aedge = (const float*)d_in[16 + o];
    const float* bias  = (const float*)d_in[17 + o];
    const float* Wsk   = (const float*)d_in[18 + o];
    const float* gam   = (const float*)d_in[19 + o];
    const float* bet   = (const float*)d_in[20 + o];
    float* out = (float*)d_out;

    cudaFuncSetAttribute(node_kernel, cudaFuncAttributeMaxDynamicSharedMemorySize, SMEM_BYTES);
    cudaFuncSetAttribute(escore_kernel, cudaFuncAttributeMaxDynamicSharedMemorySize, ESC_SMEM);

    zero_kernel<<<(NN / 4 + 255) / 256, 256>>>();
    prep_kernel<<<BB, 128>>>(ins, Wsi, bsi, Wti, bti, Wei, bei, asrc, atrg, aedge, We);
    node_kernel<<<NN / TILE_N, 256, SMEM_BYTES>>>(x, Wp, Wsk, bias, out);
    escore_kernel<<<444, 256, ESC_SMEM>>>(eidx, edges, bids);
    gather_kernel<<<NN / 8, 256>>>(eidx, gam, bet, out);
}

// round 12
// speedup vs baseline: 1.1383x; 1.0934x over previous
#include <cuda_runtime.h>

#define HH   4
#define FF   32
#define HFD  128          // H*F
#define FIN  128
#define EDIM 64
#define HID  256
#define BB   64
#define MLE  1500
#define NN   (BB*MLE)     // 96000
#define EE   600000
#define CAP  64           // per-node incidence capacity (P(overflow) ~ 1e-50)

typedef unsigned long long u64;

// ---------------- scratch (device globals; no allocation allowed) ----------
__device__ float g_proj[NN*HFD];      // 49.2 MB
__device__ float g_ss[NN*HH];
__device__ float g_st[NN*HH];
__device__ float g_s[EE*HH];          // RAW scores (exp applied in gather)
__device__ float g_usrc[BB*HFD];
__device__ float g_utrg[BB*HFD];
__device__ float g_v[BB*HH*EDIM];
__device__ unsigned g_max_ord;
__device__ int g_degt[NN];
__device__ int g_degs[NN];
__device__ int g_listt[NN*CAP];       // edge ids whose trg == n
__device__ int g_lists[NN*CAP];       // edge ids whose src == n

// ---------------- helpers --------------------------------------------------
__device__ __forceinline__ unsigned f2ord(float f) {
    unsigned b = __float_as_uint(f);
    return (b & 0x80000000u) ? ~b : (b | 0x80000000u);
}
__device__ __forceinline__ float ord2f(unsigned u) {
    unsigned b = (u & 0x80000000u) ? (u & 0x7fffffffu) : ~u;
    return __uint_as_float(b);
}
__device__ __forceinline__ float lrelu(float x) { return x > 0.f ? x : 0.2f * x; }
__device__ __forceinline__ float comp4(float4 v, int h) {
    return h == 0 ? v.x : h == 1 ? v.y : h == 2 ? v.z : v.w;
}
// packed f32x2 (sm_103a FFMA2 — only reachable via PTX)
__device__ __forceinline__ u64 pack2(float lo, float hi) {
    u64 r; asm("mov.b64 %0, {%1, %2};" : "=l"(r) : "f"(lo), "f"(hi)); return r;
}
__device__ __forceinline__ void unpack2(u64 v, float& lo, float& hi) {
    asm("mov.b64 {%0, %1}, %2;" : "=f"(lo), "=f"(hi) : "l"(v));
}
__device__ __forceinline__ u64 fma2(u64 a, u64 b, u64 c) {
    u64 d; asm("fma.rn.f32x2 %0, %1, %2, %3;" : "=l"(d) : "l"(a), "l"(b), "l"(c)); return d;
}

// ---------------- K0: zero degree counters + init max ----------------------
__global__ void zero_kernel() {
    int i = blockIdx.x * 256 + threadIdx.x;
    if (i < NN / 4) {
        ((int4*)g_degt)[i] = make_int4(0, 0, 0, 0);
        ((int4*)g_degs)[i] = make_int4(0, 0, 0, 0);
    }
    if (i == 0) g_max_ord = 0x007FFFFFu;   // encodes -inf
}

// ---------------- K1: per-batch instruction bridges ------------------------
__global__ void prep_kernel(const float* __restrict__ ins,
                            const float* __restrict__ Wsi, const float* __restrict__ bsi,
                            const float* __restrict__ Wti, const float* __restrict__ bti,
                            const float* __restrict__ Wei, const float* __restrict__ bei,
                            const float* __restrict__ asrc, const float* __restrict__ atrg,
                            const float* __restrict__ aedge, const float* __restrict__ Wedge) {
    __shared__ float si[HID];
    __shared__ float ce[HFD];
    int b = blockIdx.x, t = threadIdx.x;   // 128 threads
    for (int k = t; k < HID; k += 128) si[k] = ins[b * HID + k];
    __syncthreads();
    float s1 = bsi[t], s2 = bti[t], s3 = bei[t];
    for (int k = 0; k < HID; k++) {
        float iv = si[k];
        s1 += iv * Wsi[k * HFD + t];
        s2 += iv * Wti[k * HFD + t];
        s3 += iv * Wei[k * HFD + t];
    }
    g_usrc[b * HFD + t] = s1 * asrc[t];
    g_utrg[b * HFD + t] = s2 * atrg[t];
    ce[t] = s3 * aedge[t];
    __syncthreads();
    for (int o = t; o < HH * EDIM; o += 128) {
        int h = o >> 6, d = o & 63;
        float v = 0.f;
        #pragma unroll
        for (int f = 0; f < FF; f++) v += Wedge[d * HFD + h * FF + f] * ce[h * FF + f];
        g_v[b * HH * EDIM + o] = v;
    }
}

// ---------------- K2: fused node GEMM (FFMA2) + scores + skip init ---------
#define TILE_N 64
#define KCOLS  256
#define XPAD   132
#define SMEM_BYTES ((FIN*KCOLS + TILE_N*XPAD) * 4)

__global__ void node_kernel(const float* __restrict__ x,
                            const float* __restrict__ Wp,
                            const float* __restrict__ Wsk,
                            const float* __restrict__ bias,
                            float* __restrict__ out) {
    extern __shared__ float smem[];
    float* sW = smem;                 // [128][256]
    float* sX = smem + FIN * KCOLS;   // [64][132] padded (reused as proj tile)
    int tid = threadIdx.x;

    const float4* Wp4 = (const float4*)Wp;
    const float4* Ws4 = (const float4*)Wsk;
    for (int i4 = tid; i4 < FIN * KCOLS / 4; i4 += 256) {
        int k = i4 >> 6, c4 = i4 & 63;
        float4 v = (c4 < 32) ? Wp4[k * 32 + c4] : Ws4[k * 32 + (c4 - 32)];
        ((float4*)sW)[i4] = v;
    }
    int base = blockIdx.x * TILE_N;
    const float4* x4 = (const float4*)x;
    for (int i = tid; i < TILE_N * 32; i += 256) {
        int r = i >> 5, k4 = i & 31;
        float4 v = x4[(base + r) * 32 + k4];
        *(float4*)&sX[r * XPAD + k4 * 4] = v;
    }
    __syncthreads();

    int tcol = tid & 31, trow = tid >> 5;
    u64 acc2[8][4];
    #pragma unroll
    for (int j = 0; j < 8; j++)
        #pragma unroll
        for (int i = 0; i < 4; i++) acc2[j][i] = 0ull;

    for (int kk = 0; kk < FIN; kk += 4) {
        float4 xv4[8];
        #pragma unroll
        for (int j = 0; j < 8; j++)
            xv4[j] = *(const float4*)&sX[(trow * 8 + j) * XPAD + kk];  // broadcast
        #pragma unroll
        for (int q = 0; q < 4; q++) {
            int k = kk + q;
            u64 wr2[4];
            #pragma unroll
            for (int i = 0; i < 4; i++)
                wr2[i] = *(const u64*)&sW[k * KCOLS + 2 * (tcol + 32 * i)];
            #pragma unroll
            for (int j = 0; j < 8; j++) {
                float xv = (q == 0) ? xv4[j].x : (q == 1) ? xv4[j].y
                          : (q == 2) ? xv4[j].z : xv4[j].w;
                u64 x2 = pack2(xv, xv);
                #pragma unroll
                for (int i = 0; i < 4; i++) acc2[j][i] = fma2(x2, wr2[i], acc2[j][i]);
            }
        }
    }
    __syncthreads();

    #pragma unroll
    for (int j = 0; j < 8; j++) {
        int ln = trow * 8 + j;
        int gn = base + ln;
        #pragma unroll
        for (int i = 0; i < 4; i++) {
            int c0 = 2 * (tcol + 32 * i);
            float lo, hi; unpack2(acc2[j][i], lo, hi);
            if (i < 2) {
                *(float2*)&g_proj[gn * HFD + c0] = make_float2(lo, hi);
                sX[ln * XPAD + c0] = lo;
                sX[ln * XPAD + c0 + 1] = hi;
            } else {
                int oj = c0 - HFD;
                float o0 = lo + bias[oj];
                float o1 = hi + bias[oj + 1];
                out[(size_t)gn * 256 + oj] = o0;
                out[(size_t)gn * 256 + oj + 1] = o1;
                out[(size_t)gn * 256 + 128 + oj] = o0;
                out[(size_t)gn * 256 + 128 + oj + 1] = o1;
            }
        }
    }
    __syncthreads();

    int ln = tid & 63, h = tid >> 6;
    int gn = base + ln;
    int b = gn / MLE;
    const float* us = g_usrc + b * HFD + h * FF;
    const float* ut = g_utrg + b * HFD + h * FF;
    const float* pr = sX + ln * XPAD + h * FF;
    float a = 0.f, c2 = 0.f;
    #pragma unroll
    for (int f = 0; f < FF; f++) { float p = pr[f]; a = fmaf(p, us[f], a); c2 = fmaf(p, ut[f], c2); }
    g_ss[gn * HH + h] = a;
    g_st[gn * HH + h] = c2;
}

// ---------------- K3: per-edge scores (8 lanes/edge), v via L1 -------------
// Warp handles 4 edges. Each lane loads 32B of its edge row; v-table (64KB)
// stays L1-resident via __ldg (no smem -> 2x occupancy for latency hiding).
__global__ void escore_kernel(const int* __restrict__ eidx,
                              const float* __restrict__ edges,
                              const int* __restrict__ bids) {
    int gwarp = (blockIdx.x * 256 + threadIdx.x) >> 5;
    int nwarps = gridDim.x * 8;
    int lane = threadIdx.x & 31;
    int g = lane >> 3, l = lane & 7;
    const float4* v4 = (const float4*)g_v;

    float m = -3.4e38f;
    for (int grp = gwarp; grp < EE / 4; grp += nwarps) {
        int e = grp * 4 + g;
        int b = __ldg(bids + e);
        const float4* er = (const float4*)edges + e * 16 + l * 2;
        float4 ev0 = er[0];
        float4 ev1 = er[1];
        const float4* vb = v4 + b * 64 + l * 2;   // group-contiguous, L1-hot
        float se[HH];
        #pragma unroll
        for (int h = 0; h < HH; h++) {
            float4 v0 = __ldg(vb + h * 16);
            float4 v1 = __ldg(vb + h * 16 + 1);
            se[h] = ev0.x * v0.x + ev0.y * v0.y + ev0.z * v0.z + ev0.w * v0.w
                  + ev1.x * v1.x + ev1.y * v1.y + ev1.z * v1.z + ev1.w * v1.w;
        }
        #pragma unroll
        for (int off = 1; off < 8; off <<= 1) {
            se[0] += __shfl_xor_sync(0xffffffffu, se[0], off);
            se[1] += __shfl_xor_sync(0xffffffffu, se[1], off);
            se[2] += __shfl_xor_sync(0xffffffffu, se[2], off);
            se[3] += __shfl_xor_sync(0xffffffffu, se[3], off);
        }
        if (l == 0) {
            int src = __ldg(eidx + e), trg = __ldg(eidx + EE + e);
            float4 ss = __ldg((const float4*)g_ss + src);
            float4 st = __ldg((const float4*)g_st + trg);
            float s0 = lrelu(ss.x + st.x + se[0]);
            float s1 = lrelu(ss.y + st.y + se[1]);
            float s2 = lrelu(ss.z + st.z + se[2]);
            float s3 = lrelu(ss.w + st.w + se[3]);
            ((float4*)g_s)[e] = make_float4(s0, s1, s2, s3);   // raw scores
            m = fmaxf(m, fmaxf(fmaxf(s0, s1), fmaxf(s2, s3)));
            int pt = atomicAdd(&g_degt[trg], 1);
            if (pt < CAP) g_listt[trg * CAP + pt] = e;
            int ps = atomicAdd(&g_degs[src], 1);
            if (ps < CAP) g_lists[src * CAP + ps] = e;
        }
    }
    #pragma unroll
    for (int off = 16; off; off >>= 1) m = fmaxf(m, __shfl_xor_sync(0xffffffffu, m, off));
    __shared__ float wm[8];
    if ((threadIdx.x & 31) == 0) wm[threadIdx.x >> 5] = m;
    __syncthreads();
    if (threadIdx.x < 8) {
        m = wm[threadIdx.x];
        #pragma unroll
        for (int off = 4; off; off >>= 1) m = fmaxf(m, __shfl_xor_sync(0xffu, m, off));
        if (threadIdx.x == 0) atomicMax(&g_max_ord, f2ord(m));
    }
}

// ---------------- K4: gather: exp + denom + aggregate + skip + LayerNorm ---
__global__ void gather_kernel(const int* __restrict__ eidx,
                              const float* __restrict__ gamma,
                              const float* __restrict__ beta,
                              float* __restrict__ out) {
    __shared__ int   s_nbr[2][8][32];
    __shared__ float s_ex [2][8][32][4];
    int w = threadIdx.x >> 5;
    int n = blockIdx.x * 8 + w;
    int lane = threadIdx.x & 31;
    int h = lane >> 3;
    float M = ord2f(g_max_ord);
    int dt = g_degt[n]; if (dt > CAP) dt = CAP;
    int ds = g_degs[n]; if (ds > CAP) ds = CAP;
    int m32t = dt < 32 ? dt : 32;
    int m32s = ds < 32 ? ds : 32;
    const float4* sc4 = (const float4*)g_s;
    const float4* pr4 = (const float4*)g_proj;

    if (lane < m32t) {
        int e = g_listt[n * CAP + lane];
        s_nbr[0][w][lane] = __ldg(eidx + e);
        float4 sc = __ldg(sc4 + e);
        s_ex[0][w][lane][0] = __expf(sc.x - M);
        s_ex[0][w][lane][1] = __expf(sc.y - M);
        s_ex[0][w][lane][2] = __expf(sc.z - M);
        s_ex[0][w][lane][3] = __expf(sc.w - M);
    }
    if (lane < m32s) {
        int e = g_lists[n * CAP + lane];
        s_nbr[1][w][lane] = __ldg(eidx + EE + e);
        float4 sc = __ldg(sc4 + e);
        s_ex[1][w][lane][0] = __expf(sc.x - M);
        s_ex[1][w][lane][1] = __expf(sc.y - M);
        s_ex[1][w][lane][2] = __expf(sc.z - M);
        s_ex[1][w][lane][3] = __expf(sc.w - M);
    }
    __syncwarp();

    float dT = 0.f, dS = 0.f;
    float4 aT = make_float4(0.f, 0.f, 0.f, 0.f);
    float4 aS = make_float4(0.f, 0.f, 0.f, 0.f);
    int mmax = m32t > m32s ? m32t : m32s;
    for (int it = 0; it < mmax; it += 4) {
        #pragma unroll
        for (int j = 0; j < 4; j++) {
            int idx = it + j;
            if (idx < m32t) {
                int nbr = s_nbr[0][w][idx];           // broadcast LDS
                float a = s_ex[0][w][idx][h];         // 4-way broadcast LDS
                float4 p = __ldg(pr4 + nbr * 32 + lane);
                dT += a;
                aT.x += p.x * a; aT.y += p.y * a; aT.z += p.z * a; aT.w += p.w * a;
            }
            if (idx < m32s) {
                int nbr = s_nbr[1][w][idx];
                float a = s_ex[1][w][idx][h];
                float4 p = __ldg(pr4 + nbr * 32 + lane);
                dS += a;
                aS.x += p.x * a; aS.y += p.y * a; aS.z += p.z * a; aS.w += p.w * a;
            }
        }
    }
    // rare tails (deg > 32)
    for (int it = 32; it < dt; it++) {
        int e = g_listt[n * CAP + it];
        float a = __expf(comp4(sc4[e], h) - M);
        int nbr = eidx[e];
        float4 p = pr4[nbr * 32 + lane];
        dT += a;
        aT.x += p.x * a; aT.y += p.y * a; aT.z += p.z * a; aT.w += p.w * a;
    }
    for (int it = 32; it < ds; it++) {
        int e = g_lists[n * CAP + it];
        float a = __expf(comp4(sc4[e], h) - M);
        int nbr = eidx[EE + e];
        float4 p = pr4[nbr * 32 + lane];
        dS += a;
        aS.x += p.x * a; aS.y += p.y * a; aS.z += p.z * a; aS.w += p.w * a;
    }

    float rT = 1.f / (dT + 1e-16f);
    float rS = 1.f / (dS + 1e-16f);

    float4* row = (float4*)(out + (size_t)n * 256);
    float4 v1 = row[lane];        // skip+bias (src half)
    float4 v2 = row[32 + lane];   // skip+bias (trg half)
    v1.x += aS.x * rS; v1.y += aS.y * rS; v1.z += aS.z * rS; v1.w += aS.w * rS;
    v2.x += aT.x * rT; v2.y += aT.y * rT; v2.z += aT.z * rT; v2.w += aT.w * rT;

    // LayerNorm over 256 within the warp
    float s = v1.x + v1.y + v1.z + v1.w + v2.x + v2.y + v2.z + v2.w;
    #pragma unroll
    for (int off = 16; off; off >>= 1) s += __shfl_xor_sync(0xffffffffu, s, off);
    float mu = s * (1.f / 256.f);
    float dx, sq = 0.f;
    dx = v1.x - mu; sq += dx * dx;  dx = v1.y - mu; sq += dx * dx;
    dx = v1.z - mu; sq += dx * dx;  dx = v1.w - mu; sq += dx * dx;
    dx = v2.x - mu; sq += dx * dx;  dx = v2.y - mu; sq += dx * dx;
    dx = v2.z - mu; sq += dx * dx;  dx = v2.w - mu; sq += dx * dx;
    #pragma unroll
    for (int off = 16; off; off >>= 1) sq += __shfl_xor_sync(0xffffffffu, sq, off);
    float inv = rsqrtf(sq * (1.f / 256.f) + 1e-5f);
    float4 g1 = ((const float4*)gamma)[lane], g2 = ((const float4*)gamma)[32 + lane];
    float4 b1 = ((const float4*)beta)[lane],  b2 = ((const float4*)beta)[32 + lane];
    v1.x = (v1.x - mu) * inv * g1.x + b1.x;  v1.y = (v1.y - mu) * inv * g1.y + b1.y;
    v1.z = (v1.z - mu) * inv * g1.z + b1.z;  v1.w = (v1.w - mu) * inv * g1.w + b1.w;
    v2.x = (v2.x - mu) * inv * g2.x + b2.x;  v2.y = (v2.y - mu) * inv * g2.y + b2.y;
    v2.z = (v2.z - mu) * inv * g2.z + b2.z;  v2.w = (v2.w - mu) * inv * g2.w + b2.w;
    row[lane] = v1;
    row[32 + lane] = v2;
}

// ---------------- launch ---------------------------------------------------
extern "C" void kernel_launch(void* const* d_in, const int* in_sizes, int n_in,
                              void* d_out, int out_size) {
    int o = (in_sizes[5] == 1) ? 0 : -1;
    const float* x     = (const float*)d_in[0];
    const int*   eidx  = (const int*)  d_in[1];
    const float* edges = (const float*)d_in[2];
    const float* ins   = (const float*)d_in[3];
    const int*   bids  = (const int*)  d_in[4];
    const float* Wp    = (const float*)d_in[6 + o];
    const float* We    = (const float*)d_in[7 + o];
    const float* Wsi   = (const float*)d_in[8 + o];
    const float* bsi   = (const float*)d_in[9 + o];
    const float* Wti   = (const float*)d_in[10 + o];
    const float* bti   = (const float*)d_in[11 + o];
    const float* Wei   = (const float*)d_in[12 + o];
    const float* bei   = (const float*)d_in[13 + o];
    const float* asrc  = (const float*)d_in[14 + o];
    const float* atrg  = (const float*)d_in[15 + o];
    const float* aedge = (const float*)d_in[16 + o];
    const float* bias  = (const float*)d_in[17 + o];
    const float* Wsk   = (const float*)d_in[18 + o];
    const float* gam   = (const float*)d_in[19 + o];
    const float* bet   = (const float*)d_in[20 + o];
    float* out = (float*)d_out;

    cudaFuncSetAttribute(node_kernel, cudaFuncAttributeMaxDynamicSharedMemorySize, SMEM_BYTES);

    zero_kernel<<<(NN / 4 + 255) / 256, 256>>>();
    prep_kernel<<<BB, 128>>>(ins, Wsi, bsi, Wti, bti, Wei, bei, asrc, atrg, aedge, We);
    node_kernel<<<NN / TILE_N, 256, SMEM_BYTES>>>(x, Wp, Wsk, bias, out);
    escore_kernel<<<888, 256>>>(eidx, edges, bids);
    gather_kernel<<<NN / 8, 256>>>(eidx, gam, bet, out);
}

// round 13
// speedup vs baseline: 1.2310x; 1.0815x over previous
#include <cuda_runtime.h>

#define HH   4
#define FF   32
#define HFD  128          // H*F
#define FIN  128
#define EDIM 64
#define HID  256
#define BB   64
#define MLE  1500
#define NN   (BB*MLE)     // 96000
#define EE   600000
#define CAP  64           // per-node incidence capacity (P(overflow) ~ 1e-50)

typedef unsigned long long u64;

// ---------------- scratch (device globals; no allocation allowed) ----------
__device__ float g_proj[NN*HFD];      // 49.2 MB
__device__ float g_ss[NN*HH];
__device__ float g_st[NN*HH];
__device__ float g_s[EE*HH];          // RAW scores (exp applied in gather)
__device__ float g_usrc[BB*HFD];
__device__ float g_utrg[BB*HFD];
__device__ float g_v[BB*HH*EDIM];
__device__ unsigned g_max_ord;
__device__ int g_degt[NN];
__device__ int g_degs[NN];
__device__ int g_listt[NN*CAP];       // edge ids whose trg == n
__device__ int g_lists[NN*CAP];       // edge ids whose src == n

// ---------------- helpers --------------------------------------------------
__device__ __forceinline__ unsigned f2ord(float f) {
    unsigned b = __float_as_uint(f);
    return (b & 0x80000000u) ? ~b : (b | 0x80000000u);
}
__device__ __forceinline__ float ord2f(unsigned u) {
    unsigned b = (u & 0x80000000u) ? (u & 0x7fffffffu) : ~u;
    return __uint_as_float(b);
}
__device__ __forceinline__ float lrelu(float x) { return x > 0.f ? x : 0.2f * x; }
__device__ __forceinline__ float comp4(float4 v, int h) {
    return h == 0 ? v.x : h == 1 ? v.y : h == 2 ? v.z : v.w;
}
// packed f32x2 (sm_103a FFMA2 — only reachable via PTX)
__device__ __forceinline__ u64 pack2(float lo, float hi) {
    u64 r; asm("mov.b64 %0, {%1, %2};" : "=l"(r) : "f"(lo), "f"(hi)); return r;
}
__device__ __forceinline__ void unpack2(u64 v, float& lo, float& hi) {
    asm("mov.b64 {%0, %1}, %2;" : "=f"(lo), "=f"(hi) : "l"(v));
}
__device__ __forceinline__ u64 fma2(u64 a, u64 b, u64 c) {
    u64 d; asm("fma.rn.f32x2 %0, %1, %2, %3;" : "=l"(d) : "l"(a), "l"(b), "l"(c)); return d;
}

// ---------------- K0: zero degree counters + init max ----------------------
__global__ void zero_kernel() {
    int i = blockIdx.x * 256 + threadIdx.x;
    if (i < NN / 4) {
        ((int4*)g_degt)[i] = make_int4(0, 0, 0, 0);
        ((int4*)g_degs)[i] = make_int4(0, 0, 0, 0);
    }
    if (i == 0) g_max_ord = 0x007FFFFFu;   // encodes -inf
}

// ---------------- K1: per-batch instruction bridges ------------------------
__global__ void prep_kernel(const float* __restrict__ ins,
                            const float* __restrict__ Wsi, const float* __restrict__ bsi,
                            const float* __restrict__ Wti, const float* __restrict__ bti,
                            const float* __restrict__ Wei, const float* __restrict__ bei,
                            const float* __restrict__ asrc, const float* __restrict__ atrg,
                            const float* __restrict__ aedge, const float* __restrict__ Wedge) {
    __shared__ float si[HID];
    __shared__ float ce[HFD];
    int b = blockIdx.x, t = threadIdx.x;   // 128 threads
    for (int k = t; k < HID; k += 128) si[k] = ins[b * HID + k];
    __syncthreads();
    float s1 = bsi[t], s2 = bti[t], s3 = bei[t];
    for (int k = 0; k < HID; k++) {
        float iv = si[k];
        s1 += iv * Wsi[k * HFD + t];
        s2 += iv * Wti[k * HFD + t];
        s3 += iv * Wei[k * HFD + t];
    }
    g_usrc[b * HFD + t] = s1 * asrc[t];
    g_utrg[b * HFD + t] = s2 * atrg[t];
    ce[t] = s3 * aedge[t];
    __syncthreads();
    for (int o = t; o < HH * EDIM; o += 128) {
        int h = o >> 6, d = o & 63;
        float v = 0.f;
        #pragma unroll
        for (int f = 0; f < FF; f++) v += Wedge[d * HFD + h * FF + f] * ce[h * FF + f];
        g_v[b * HH * EDIM + o] = v;
    }
}

// ---------------- K2: fused node GEMM (FFMA2) + scores + skip init ---------
// TILE_N=128, 512 threads: halves per-row W staging vs TILE_N=64 and gives
// 16 warps for latency hiding (194 KB smem, 1 block/SM).
#define TILE_N 128
#define NTHR   512
#define KCOLS  256
#define XPAD   132
#define SMEM_BYTES ((FIN*KCOLS + TILE_N*XPAD) * 4)

__global__ void __launch_bounds__(NTHR, 1)
node_kernel(const float* __restrict__ x,
            const float* __restrict__ Wp,
            const float* __restrict__ Wsk,
            const float* __restrict__ bias,
            float* __restrict__ out) {
    extern __shared__ float smem[];
    float* sW = smem;                 // [128][256]
    float* sX = smem + FIN * KCOLS;   // [128][132] padded (reused as proj tile)
    int tid = threadIdx.x;

    const float4* Wp4 = (const float4*)Wp;
    const float4* Ws4 = (const float4*)Wsk;
    for (int i4 = tid; i4 < FIN * KCOLS / 4; i4 += NTHR) {
        int k = i4 >> 6, c4 = i4 & 63;
        float4 v = (c4 < 32) ? Wp4[k * 32 + c4] : Ws4[k * 32 + (c4 - 32)];
        ((float4*)sW)[i4] = v;
    }
    int base = blockIdx.x * TILE_N;
    const float4* x4 = (const float4*)x;
    for (int i = tid; i < TILE_N * 32; i += NTHR) {
        int r = i >> 5, k4 = i & 31;
        float4 v = x4[(base + r) * 32 + k4];
        *(float4*)&sX[r * XPAD + k4 * 4] = v;
    }
    __syncthreads();

    int tcol = tid & 31, trow = tid >> 5;   // 16 warps x 8 rows = 128 rows
    u64 acc2[8][4];
    #pragma unroll
    for (int j = 0; j < 8; j++)
        #pragma unroll
        for (int i = 0; i < 4; i++) acc2[j][i] = 0ull;

    for (int kk = 0; kk < FIN; kk += 4) {
        float4 xv4[8];
        #pragma unroll
        for (int j = 0; j < 8; j++)
            xv4[j] = *(const float4*)&sX[(trow * 8 + j) * XPAD + kk];  // broadcast
        #pragma unroll
        for (int q = 0; q < 4; q++) {
            int k = kk + q;
            u64 wr2[4];
            #pragma unroll
            for (int i = 0; i < 4; i++)
                wr2[i] = *(const u64*)&sW[k * KCOLS + 2 * (tcol + 32 * i)];
            #pragma unroll
            for (int j = 0; j < 8; j++) {
                float xv = (q == 0) ? xv4[j].x : (q == 1) ? xv4[j].y
                          : (q == 2) ? xv4[j].z : xv4[j].w;
                u64 x2 = pack2(xv, xv);
                #pragma unroll
                for (int i = 0; i < 4; i++) acc2[j][i] = fma2(x2, wr2[i], acc2[j][i]);
            }
        }
    }
    __syncthreads();

    #pragma unroll
    for (int j = 0; j < 8; j++) {
        int ln = trow * 8 + j;
        int gn = base + ln;
        #pragma unroll
        for (int i = 0; i < 4; i++) {
            int c0 = 2 * (tcol + 32 * i);
            float lo, hi; unpack2(acc2[j][i], lo, hi);
            if (i < 2) {
                *(float2*)&g_proj[gn * HFD + c0] = make_float2(lo, hi);
                sX[ln * XPAD + c0] = lo;
                sX[ln * XPAD + c0 + 1] = hi;
            } else {
                int oj = c0 - HFD;
                float o0 = lo + bias[oj];
                float o1 = hi + bias[oj + 1];
                out[(size_t)gn * 256 + oj] = o0;
                out[(size_t)gn * 256 + oj + 1] = o1;
                out[(size_t)gn * 256 + 128 + oj] = o0;
                out[(size_t)gn * 256 + 128 + oj + 1] = o1;
            }
        }
    }
    __syncthreads();

    int ln = tid & 127, h = tid >> 7;       // 512 threads = 128 nodes x 4 heads
    int gn = base + ln;
    int b = gn / MLE;
    const float* us = g_usrc + b * HFD + h * FF;
    const float* ut = g_utrg + b * HFD + h * FF;
    const float* pr = sX + ln * XPAD + h * FF;
    float a = 0.f, c2 = 0.f;
    #pragma unroll
    for (int f = 0; f < FF; f++) { float p = pr[f]; a = fmaf(p, us[f], a); c2 = fmaf(p, ut[f], c2); }
    g_ss[gn * HH + h] = a;
    g_st[gn * HH + h] = c2;
}

// ---------------- K3: per-edge scores (8 lanes/edge), 1-line-per-group LDGs
// Lane l owns edge chunk l (first 128B) and chunk 8+l (second 128B): every
// LDG covers exactly one 128B line per 8-lane group -> 4 lines/warp-LDG.
__global__ void escore_kernel(const int* __restrict__ eidx,
                              const float* __restrict__ edges,
                              const int* __restrict__ bids) {
    int gwarp = (blockIdx.x * 256 + threadIdx.x) >> 5;
    int nwarps = gridDim.x * 8;
    int lane = threadIdx.x & 31;
    int g = lane >> 3, l = lane & 7;
    const float4* v4 = (const float4*)g_v;

    float m = -3.4e38f;
    for (int grp = gwarp; grp < EE / 4; grp += nwarps) {
        int e = grp * 4 + g;
        int b = __ldg(bids + e);
        const float4* er = (const float4*)edges + e * 16;
        float4 ea = er[l];        // chunk l      (line 0 of row)
        float4 eb = er[8 + l];    // chunk 8+l    (line 1 of row)
        const float4* vb = v4 + b * 64;
        float se[HH];
        #pragma unroll
        for (int h = 0; h < HH; h++) {
            float4 va = __ldg(vb + h * 16 + l);       // 1 line/group
            float4 vc = __ldg(vb + h * 16 + 8 + l);   // 1 line/group
            se[h] = ea.x * va.x + ea.y * va.y + ea.z * va.z + ea.w * va.w
                  + eb.x * vc.x + eb.y * vc.y + eb.z * vc.z + eb.w * vc.w;
        }
        #pragma unroll
        for (int off = 1; off < 8; off <<= 1) {
            se[0] += __shfl_xor_sync(0xffffffffu, se[0], off);
            se[1] += __shfl_xor_sync(0xffffffffu, se[1], off);
            se[2] += __shfl_xor_sync(0xffffffffu, se[2], off);
            se[3] += __shfl_xor_sync(0xffffffffu, se[3], off);
        }
        if (l == 0) {
            int src = __ldg(eidx + e), trg = __ldg(eidx + EE + e);
            float4 ss = __ldg((const float4*)g_ss + src);
            float4 st = __ldg((const float4*)g_st + trg);
            float s0 = lrelu(ss.x + st.x + se[0]);
            float s1 = lrelu(ss.y + st.y + se[1]);
            float s2 = lrelu(ss.z + st.z + se[2]);
            float s3 = lrelu(ss.w + st.w + se[3]);
            ((float4*)g_s)[e] = make_float4(s0, s1, s2, s3);   // raw scores
            m = fmaxf(m, fmaxf(fmaxf(s0, s1), fmaxf(s2, s3)));
            int pt = atomicAdd(&g_degt[trg], 1);
            if (pt < CAP) g_listt[trg * CAP + pt] = e;
            int ps = atomicAdd(&g_degs[src], 1);
            if (ps < CAP) g_lists[src * CAP + ps] = e;
        }
    }
    #pragma unroll
    for (int off = 16; off; off >>= 1) m = fmaxf(m, __shfl_xor_sync(0xffffffffu, m, off));
    __shared__ float wm[8];
    if ((threadIdx.x & 31) == 0) wm[threadIdx.x >> 5] = m;
    __syncthreads();
    if (threadIdx.x < 8) {
        m = wm[threadIdx.x];
        #pragma unroll
        for (int off = 4; off; off >>= 1) m = fmaxf(m, __shfl_xor_sync(0xffu, m, off));
        if (threadIdx.x == 0) atomicMax(&g_max_ord, f2ord(m));
    }
}

// ---------------- K4: gather: exp + denom + aggregate + skip + LayerNorm ---
__global__ void gather_kernel(const int* __restrict__ eidx,
                              const float* __restrict__ gamma,
                              const float* __restrict__ beta,
                              float* __restrict__ out) {
    __shared__ int   s_nbr[2][8][32];
    __shared__ float s_ex [2][8][32][4];
    int w = threadIdx.x >> 5;
    int n = blockIdx.x * 8 + w;
    int lane = threadIdx.x & 31;
    int h = lane >> 3;
    float M = ord2f(g_max_ord);
    int dt = g_degt[n]; if (dt > CAP) dt = CAP;
    int ds = g_degs[n]; if (ds > CAP) ds = CAP;
    int m32t = dt < 32 ? dt : 32;
    int m32s = ds < 32 ? ds : 32;
    const float4* sc4 = (const float4*)g_s;
    const float4* pr4 = (const float4*)g_proj;

    if (lane < m32t) {
        int e = g_listt[n * CAP + lane];
        s_nbr[0][w][lane] = __ldg(eidx + e);
        float4 sc = __ldg(sc4 + e);
        s_ex[0][w][lane][0] = __expf(sc.x - M);
        s_ex[0][w][lane][1] = __expf(sc.y - M);
        s_ex[0][w][lane][2] = __expf(sc.z - M);
        s_ex[0][w][lane][3] = __expf(sc.w - M);
    }
    if (lane < m32s) {
        int e = g_lists[n * CAP + lane];
        s_nbr[1][w][lane] = __ldg(eidx + EE + e);
        float4 sc = __ldg(sc4 + e);
        s_ex[1][w][lane][0] = __expf(sc.x - M);
        s_ex[1][w][lane][1] = __expf(sc.y - M);
        s_ex[1][w][lane][2] = __expf(sc.z - M);
        s_ex[1][w][lane][3] = __expf(sc.w - M);
    }
    __syncwarp();

    float dT = 0.f, dS = 0.f;
    float4 aT = make_float4(0.f, 0.f, 0.f, 0.f);
    float4 aS = make_float4(0.f, 0.f, 0.f, 0.f);
    int mmax = m32t > m32s ? m32t : m32s;
    for (int it = 0; it < mmax; it += 4) {
        #pragma unroll
        for (int j = 0; j < 4; j++) {
            int idx = it + j;
            if (idx < m32t) {
                int nbr = s_nbr[0][w][idx];           // broadcast LDS
                float a = s_ex[0][w][idx][h];         // 4-way broadcast LDS
                float4 p = __ldg(pr4 + nbr * 32 + lane);
                dT += a;
                aT.x += p.x * a; aT.y += p.y * a; aT.z += p.z * a; aT.w += p.w * a;
            }
            if (idx < m32s) {
                int nbr = s_nbr[1][w][idx];
                float a = s_ex[1][w][idx][h];
                float4 p = __ldg(pr4 + nbr * 32 + lane);
                dS += a;
                aS.x += p.x * a; aS.y += p.y * a; aS.z += p.z * a; aS.w += p.w * a;
            }
        }
    }
    // rare tails (deg > 32)
    for (int it = 32; it < dt; it++) {
        int e = g_listt[n * CAP + it];
        float a = __expf(comp4(sc4[e], h) - M);
        int nbr = eidx[e];
        float4 p = pr4[nbr * 32 + lane];
        dT += a;
        aT.x += p.x * a; aT.y += p.y * a; aT.z += p.z * a; aT.w += p.w * a;
    }
    for (int it = 32; it < ds; it++) {
        int e = g_lists[n * CAP + it];
        float a = __expf(comp4(sc4[e], h) - M);
        int nbr = eidx[EE + e];
        float4 p = pr4[nbr * 32 + lane];
        dS += a;
        aS.x += p.x * a; aS.y += p.y * a; aS.z += p.z * a; aS.w += p.w * a;
    }

    float rT = 1.f / (dT + 1e-16f);
    float rS = 1.f / (dS + 1e-16f);

    float4* row = (float4*)(out + (size_t)n * 256);
    float4 v1 = row[lane];        // skip+bias (src half)
    float4 v2 = row[32 + lane];   // skip+bias (trg half)
    v1.x += aS.x * rS; v1.y += aS.y * rS; v1.z += aS.z * rS; v1.w += aS.w * rS;
    v2.x += aT.x * rT; v2.y += aT.y * rT; v2.z += aT.z * rT; v2.w += aT.w * rT;

    // LayerNorm over 256 within the warp
    float s = v1.x + v1.y + v1.z + v1.w + v2.x + v2.y + v2.z + v2.w;
    #pragma unroll
    for (int off = 16; off; off >>= 1) s += __shfl_xor_sync(0xffffffffu, s, off);
    float mu = s * (1.f / 256.f);
    float dx, sq = 0.f;
    dx = v1.x - mu; sq += dx * dx;  dx = v1.y - mu; sq += dx * dx;
    dx = v1.z - mu; sq += dx * dx;  dx = v1.w - mu; sq += dx * dx;
    dx = v2.x - mu; sq += dx * dx;  dx = v2.y - mu; sq += dx * dx;
    dx = v2.z - mu; sq += dx * dx;  dx = v2.w - mu; sq += dx * dx;
    #pragma unroll
    for (int off = 16; off; off >>= 1) sq += __shfl_xor_sync(0xffffffffu, sq, off);
    float inv = rsqrtf(sq * (1.f / 256.f) + 1e-5f);
    float4 g1 = ((const float4*)gamma)[lane], g2 = ((const float4*)gamma)[32 + lane];
    float4 b1 = ((const float4*)beta)[lane],  b2 = ((const float4*)beta)[32 + lane];
    v1.x = (v1.x - mu) * inv * g1.x + b1.x;  v1.y = (v1.y - mu) * inv * g1.y + b1.y;
    v1.z = (v1.z - mu) * inv * g1.z + b1.z;  v1.w = (v1.w - mu) * inv * g1.w + b1.w;
    v2.x = (v2.x - mu) * inv * g2.x + b2.x;  v2.y = (v2.y - mu) * inv * g2.y + b2.y;
    v2.z = (v2.z - mu) * inv * g2.z + b2.z;  v2.w = (v2.w - mu) * inv * g2.w + b2.w;
    row[lane] = v1;
    row[32 + lane] = v2;
}

// ---------------- launch ---------------------------------------------------
extern "C" void kernel_launch(void* const* d_in, const int* in_sizes, int n_in,
                              void* d_out, int out_size) {
    int o = (in_sizes[5] == 1) ? 0 : -1;
    const float* x     = (const float*)d_in[0];
    const int*   eidx  = (const int*)  d_in[1];
    const float* edges = (const float*)d_in[2];
    const float* ins   = (const float*)d_in[3];
    const int*   bids  = (const int*)  d_in[4];
    const float* Wp    = (const float*)d_in[6 + o];
    const float* We    = (const float*)d_in[7 + o];
    const float* Wsi   = (const float*)d_in[8 + o];
    const float* bsi   = (const float*)d_in[9 + o];
    const float* Wti   = (const float*)d_in[10 + o];
    const float* bti   = (const float*)d_in[11 + o];
    const float* Wei   = (const float*)d_in[12 + o];
    const float* bei   = (const float*)d_in[13 + o];
    const float* asrc  = (const float*)d_in[14 + o];
    const float* atrg  = (const float*)d_in[15 + o];
    const float* aedge = (const float*)d_in[16 + o];
    const float* bias  = (const float*)d_in[17 + o];
    const float* Wsk   = (const float*)d_in[18 + o];
    const float* gam   = (const float*)d_in[19 + o];
    const float* bet   = (const float*)d_in[20 + o];
    float* out = (float*)d_out;

    cudaFuncSetAttribute(node_kernel, cudaFuncAttributeMaxDynamicSharedMemorySize, SMEM_BYTES);

    zero_kernel<<<(NN / 4 + 255) / 256, 256>>>();
    prep_kernel<<<BB, 128>>>(ins, Wsi, bsi, Wti, bti, Wei, bei, asrc, atrg, aedge, We);
    node_kernel<<<NN / TILE_N, NTHR, SMEM_BYTES>>>(x, Wp, Wsk, bias, out);
    escore_kernel<<<888, 256>>>(eidx, edges, bids);
    gather_kernel<<<NN / 8, 256>>>(eidx, gam, bet, out);
}

// round 14
// speedup vs baseline: 1.2967x; 1.0534x over previous
#include <cuda_runtime.h>

#define HH   4
#define FF   32
#define HFD  128          // H*F
#define FIN  128
#define EDIM 64
#define HID  256
#define BB   64
#define MLE  1500
#define NN   (BB*MLE)     // 96000
#define EE   600000
#define CAP  64           // per-node incidence capacity (P(overflow) ~ 1e-50)

typedef unsigned long long u64;

// ---------------- scratch (device globals; no allocation allowed) ----------
__device__ float g_proj[NN*HFD];      // 49.2 MB
__device__ float g_ss[NN*HH];
__device__ float g_st[NN*HH];
__device__ float g_usrc[BB*HFD];
__device__ float g_utrg[BB*HFD];
__device__ float g_v[BB*HH*EDIM];
__device__ unsigned g_max_ord;
__device__ int    g_degt[NN];
__device__ int    g_degs[NN];
__device__ int    g_nbrt[NN*CAP];     // src endpoint of edges whose trg == n
__device__ int    g_nbrs[NN*CAP];     // trg endpoint of edges whose src == n
__device__ float4 g_sct[NN*CAP];      // raw score4 of those edges (98 MB)
__device__ float4 g_scs[NN*CAP];      // raw score4 (98 MB)

// ---------------- helpers --------------------------------------------------
__device__ __forceinline__ unsigned f2ord(float f) {
    unsigned b = __float_as_uint(f);
    return (b & 0x80000000u) ? ~b : (b | 0x80000000u);
}
__device__ __forceinline__ float ord2f(unsigned u) {
    unsigned b = (u & 0x80000000u) ? (u & 0x7fffffffu) : ~u;
    return __uint_as_float(b);
}
__device__ __forceinline__ float lrelu(float x) { return x > 0.f ? x : 0.2f * x; }
__device__ __forceinline__ float comp4(float4 v, int h) {
    return h == 0 ? v.x : h == 1 ? v.y : h == 2 ? v.z : v.w;
}
// packed f32x2 (sm_103a FFMA2 — only reachable via PTX)
__device__ __forceinline__ u64 pack2(float lo, float hi) {
    u64 r; asm("mov.b64 %0, {%1, %2};" : "=l"(r) : "f"(lo), "f"(hi)); return r;
}
__device__ __forceinline__ void unpack2(u64 v, float& lo, float& hi) {
    asm("mov.b64 {%0, %1}, %2;" : "=f"(lo), "=f"(hi) : "l"(v));
}
__device__ __forceinline__ u64 fma2(u64 a, u64 b, u64 c) {
    u64 d; asm("fma.rn.f32x2 %0, %1, %2, %3;" : "=l"(d) : "l"(a), "l"(b), "l"(c)); return d;
}

// ---------------- K0: zero degree counters + init max ----------------------
__global__ void zero_kernel() {
    int i = blockIdx.x * 256 + threadIdx.x;
    if (i < NN / 4) {
        ((int4*)g_degt)[i] = make_int4(0, 0, 0, 0);
        ((int4*)g_degs)[i] = make_int4(0, 0, 0, 0);
    }
    if (i == 0) g_max_ord = 0x007FFFFFu;   // encodes -inf
}

// ---------------- K1: per-batch instruction bridges ------------------------
__global__ void prep_kernel(const float* __restrict__ ins,
                            const float* __restrict__ Wsi, const float* __restrict__ bsi,
                            const float* __restrict__ Wti, const float* __restrict__ bti,
                            const float* __restrict__ Wei, const float* __restrict__ bei,
                            const float* __restrict__ asrc, const float* __restrict__ atrg,
                            const float* __restrict__ aedge, const float* __restrict__ Wedge) {
    __shared__ float si[HID];
    __shared__ float ce[HFD];
    int b = blockIdx.x, t = threadIdx.x;   // 128 threads
    for (int k = t; k < HID; k += 128) si[k] = ins[b * HID + k];
    __syncthreads();
    float s1 = bsi[t], s2 = bti[t], s3 = bei[t];
    for (int k = 0; k < HID; k++) {
        float iv = si[k];
        s1 += iv * Wsi[k * HFD + t];
        s2 += iv * Wti[k * HFD + t];
        s3 += iv * Wei[k * HFD + t];
    }
    g_usrc[b * HFD + t] = s1 * asrc[t];
    g_utrg[b * HFD + t] = s2 * atrg[t];
    ce[t] = s3 * aedge[t];
    __syncthreads();
    for (int o = t; o < HH * EDIM; o += 128) {
        int h = o >> 6, d = o & 63;
        float v = 0.f;
        #pragma unroll
        for (int f = 0; f < FF; f++) v += Wedge[d * HFD + h * FF + f] * ce[h * FF + f];
        g_v[b * HH * EDIM + o] = v;
    }
}

// ---------------- K2: fused node GEMM (FFMA2) + scores + skip init ---------
// TILE_N=128, 512 threads. Skip+bias written ONLY to the first half of out;
// gather derives both halves from it.
#define TILE_N 128
#define NTHR   512
#define KCOLS  256
#define XPAD   132
#define SMEM_BYTES ((FIN*KCOLS + TILE_N*XPAD) * 4)

__global__ void __launch_bounds__(NTHR, 1)
node_kernel(const float* __restrict__ x,
            const float* __restrict__ Wp,
            const float* __restrict__ Wsk,
            const float* __restrict__ bias,
            float* __restrict__ out) {
    extern __shared__ float smem[];
    float* sW = smem;                 // [128][256]
    float* sX = smem + FIN * KCOLS;   // [128][132] padded (reused as proj tile)
    int tid = threadIdx.x;

    const float4* Wp4 = (const float4*)Wp;
    const float4* Ws4 = (const float4*)Wsk;
    for (int i4 = tid; i4 < FIN * KCOLS / 4; i4 += NTHR) {
        int k = i4 >> 6, c4 = i4 & 63;
        float4 v = (c4 < 32) ? Wp4[k * 32 + c4] : Ws4[k * 32 + (c4 - 32)];
        ((float4*)sW)[i4] = v;
    }
    int base = blockIdx.x * TILE_N;
    const float4* x4 = (const float4*)x;
    for (int i = tid; i < TILE_N * 32; i += NTHR) {
        int r = i >> 5, k4 = i & 31;
        float4 v = x4[(base + r) * 32 + k4];
        *(float4*)&sX[r * XPAD + k4 * 4] = v;
    }
    __syncthreads();

    int tcol = tid & 31, trow = tid >> 5;   // 16 warps x 8 rows = 128 rows
    u64 acc2[8][4];
    #pragma unroll
    for (int j = 0; j < 8; j++)
        #pragma unroll
        for (int i = 0; i < 4; i++) acc2[j][i] = 0ull;

    for (int kk = 0; kk < FIN; kk += 4) {
        float4 xv4[8];
        #pragma unroll
        for (int j = 0; j < 8; j++)
            xv4[j] = *(const float4*)&sX[(trow * 8 + j) * XPAD + kk];  // broadcast
        #pragma unroll
        for (int q = 0; q < 4; q++) {
            int k = kk + q;
            u64 wr2[4];
            #pragma unroll
            for (int i = 0; i < 4; i++)
                wr2[i] = *(const u64*)&sW[k * KCOLS + 2 * (tcol + 32 * i)];
            #pragma unroll
            for (int j = 0; j < 8; j++) {
                float xv = (q == 0) ? xv4[j].x : (q == 1) ? xv4[j].y
                          : (q == 2) ? xv4[j].z : xv4[j].w;
                u64 x2 = pack2(xv, xv);
                #pragma unroll
                for (int i = 0; i < 4; i++) acc2[j][i] = fma2(x2, wr2[i], acc2[j][i]);
            }
        }
    }
    __syncthreads();

    #pragma unroll
    for (int j = 0; j < 8; j++) {
        int ln = trow * 8 + j;
        int gn = base + ln;
        #pragma unroll
        for (int i = 0; i < 4; i++) {
            int c0 = 2 * (tcol + 32 * i);
            float lo, hi; unpack2(acc2[j][i], lo, hi);
            if (i < 2) {
                *(float2*)&g_proj[gn * HFD + c0] = make_float2(lo, hi);
                sX[ln * XPAD + c0] = lo;
                sX[ln * XPAD + c0 + 1] = hi;
            } else {
                int oj = c0 - HFD;
                out[(size_t)gn * 256 + oj] = lo + bias[oj];         // first half only
                out[(size_t)gn * 256 + oj + 1] = hi + bias[oj + 1];
            }
        }
    }
    __syncthreads();

    int ln = tid & 127, h = tid >> 7;       // 512 threads = 128 nodes x 4 heads
    int gn = base + ln;
    int b = gn / MLE;
    const float* us = g_usrc + b * HFD + h * FF;
    const float* ut = g_utrg + b * HFD + h * FF;
    const float* pr = sX + ln * XPAD + h * FF;
    float a = 0.f, c2 = 0.f;
    #pragma unroll
    for (int f = 0; f < FF; f++) { float p = pr[f]; a = fmaf(p, us[f], a); c2 = fmaf(p, ut[f], c2); }
    g_ss[gn * HH + h] = a;
    g_st[gn * HH + h] = c2;
}

// ---------------- K3: per-edge scores (8 lanes/edge) + packed lists --------
// After the 8-lane reduction ALL lanes hold the sums: lane 0 fills the trg
// list, lane 1 the src list (nbr + raw score4 packed -> gather reads
// coalesced, no random gathers left).
__global__ void escore_kernel(const int* __restrict__ eidx,
                              const float* __restrict__ edges,
                              const int* __restrict__ bids) {
    int gwarp = (blockIdx.x * 256 + threadIdx.x) >> 5;
    int nwarps = gridDim.x * 8;
    int lane = threadIdx.x & 31;
    int g = lane >> 3, l = lane & 7;
    const float4* v4 = (const float4*)g_v;

    float m = -3.4e38f;
    for (int grp = gwarp; grp < EE / 4; grp += nwarps) {
        int e = grp * 4 + g;
        int b = __ldg(bids + e);
        const float4* er = (const float4*)edges + e * 16;
        float4 ea = er[l];        // chunk l      (line 0 of row)
        float4 eb = er[8 + l];    // chunk 8+l    (line 1 of row)
        const float4* vb = v4 + b * 64;
        float se[HH];
        #pragma unroll
        for (int h = 0; h < HH; h++) {
            float4 va = __ldg(vb + h * 16 + l);       // 1 line/group
            float4 vc = __ldg(vb + h * 16 + 8 + l);   // 1 line/group
            se[h] = ea.x * va.x + ea.y * va.y + ea.z * va.z + ea.w * va.w
                  + eb.x * vc.x + eb.y * vc.y + eb.z * vc.z + eb.w * vc.w;
        }
        #pragma unroll
        for (int off = 1; off < 8; off <<= 1) {
            se[0] += __shfl_xor_sync(0xffffffffu, se[0], off);
            se[1] += __shfl_xor_sync(0xffffffffu, se[1], off);
            se[2] += __shfl_xor_sync(0xffffffffu, se[2], off);
            se[3] += __shfl_xor_sync(0xffffffffu, se[3], off);
        }
        if (l < 2) {
            int src = __ldg(eidx + e), trg = __ldg(eidx + EE + e);
            float4 ss = __ldg((const float4*)g_ss + src);   // same addr both lanes
            float4 st = __ldg((const float4*)g_st + trg);
            float s0 = lrelu(ss.x + st.x + se[0]);
            float s1 = lrelu(ss.y + st.y + se[1]);
            float s2 = lrelu(ss.z + st.z + se[2]);
            float s3 = lrelu(ss.w + st.w + se[3]);
            if (l == 0) {
                m = fmaxf(m, fmaxf(fmaxf(s0, s1), fmaxf(s2, s3)));
                int pt = atomicAdd(&g_degt[trg], 1);
                if (pt < CAP) {
                    g_nbrt[trg * CAP + pt] = src;
                    g_sct[trg * CAP + pt] = make_float4(s0, s1, s2, s3);
                }
            } else {
                int ps = atomicAdd(&g_degs[src], 1);
                if (ps < CAP) {
                    g_nbrs[src * CAP + ps] = trg;
                    g_scs[src * CAP + ps] = make_float4(s0, s1, s2, s3);
                }
            }
        }
    }
    #pragma unroll
    for (int off = 16; off; off >>= 1) m = fmaxf(m, __shfl_xor_sync(0xffffffffu, m, off));
    __shared__ float wm[8];
    if ((threadIdx.x & 31) == 0) wm[threadIdx.x >> 5] = m;
    __syncthreads();
    if (threadIdx.x < 8) {
        m = wm[threadIdx.x];
        #pragma unroll
        for (int off = 4; off; off >>= 1) m = fmaxf(m, __shfl_xor_sync(0xffu, m, off));
        if (threadIdx.x == 0) atomicMax(&g_max_ord, f2ord(m));
    }
}

// ---------------- K4: gather: exp + denom + aggregate + skip + LayerNorm ---
// Staging reads are now fully coalesced (nbr + score4 packed per node slot).
__global__ void gather_kernel(const float* __restrict__ gamma,
                              const float* __restrict__ beta,
                              float* __restrict__ out) {
    __shared__ int   s_nbr[2][8][32];
    __shared__ float s_ex [2][8][32][4];
    int w = threadIdx.x >> 5;
    int n = blockIdx.x * 8 + w;
    int lane = threadIdx.x & 31;
    int h = lane >> 3;
    float M = ord2f(g_max_ord);
    int dt = g_degt[n]; if (dt > CAP) dt = CAP;
    int ds = g_degs[n]; if (ds > CAP) ds = CAP;
    int m32t = dt < 32 ? dt : 32;
    int m32s = ds < 32 ? ds : 32;
    const float4* pr4 = (const float4*)g_proj;

    if (lane < m32t) {
        s_nbr[0][w][lane] = __ldg(g_nbrt + n * CAP + lane);     // coalesced
        float4 sc = __ldg(g_sct + n * CAP + lane);              // coalesced
        s_ex[0][w][lane][0] = __expf(sc.x - M);
        s_ex[0][w][lane][1] = __expf(sc.y - M);
        s_ex[0][w][lane][2] = __expf(sc.z - M);
        s_ex[0][w][lane][3] = __expf(sc.w - M);
    }
    if (lane < m32s) {
        s_nbr[1][w][lane] = __ldg(g_nbrs + n * CAP + lane);
        float4 sc = __ldg(g_scs + n * CAP + lane);
        s_ex[1][w][lane][0] = __expf(sc.x - M);
        s_ex[1][w][lane][1] = __expf(sc.y - M);
        s_ex[1][w][lane][2] = __expf(sc.z - M);
        s_ex[1][w][lane][3] = __expf(sc.w - M);
    }
    __syncwarp();

    float dT = 0.f, dS = 0.f;
    float4 aT = make_float4(0.f, 0.f, 0.f, 0.f);
    float4 aS = make_float4(0.f, 0.f, 0.f, 0.f);
    int mmax = m32t > m32s ? m32t : m32s;
    for (int it = 0; it < mmax; it += 4) {
        #pragma unroll
        for (int j = 0; j < 4; j++) {
            int idx = it + j;
            if (idx < m32t) {
                int nbr = s_nbr[0][w][idx];           // broadcast LDS
                float a = s_ex[0][w][idx][h];         // 4-way broadcast LDS
                float4 p = __ldg(pr4 + nbr * 32 + lane);
                dT += a;
                aT.x += p.x * a; aT.y += p.y * a; aT.z += p.z * a; aT.w += p.w * a;
            }
            if (idx < m32s) {
                int nbr = s_nbr[1][w][idx];
                float a = s_ex[1][w][idx][h];
                float4 p = __ldg(pr4 + nbr * 32 + lane);
                dS += a;
                aS.x += p.x * a; aS.y += p.y * a; aS.z += p.z * a; aS.w += p.w * a;
            }
        }
    }
    // rare tails (deg > 32)
    for (int it = 32; it < dt; it++) {
        int nbr = g_nbrt[n * CAP + it];
        float a = __expf(comp4(g_sct[n * CAP + it], h) - M);
        float4 p = pr4[nbr * 32 + lane];
        dT += a;
        aT.x += p.x * a; aT.y += p.y * a; aT.z += p.z * a; aT.w += p.w * a;
    }
    for (int it = 32; it < ds; it++) {
        int nbr = g_nbrs[n * CAP + it];
        float a = __expf(comp4(g_scs[n * CAP + it], h) - M);
        float4 p = pr4[nbr * 32 + lane];
        dS += a;
        aS.x += p.x * a; aS.y += p.y * a; aS.z += p.z * a; aS.w += p.w * a;
    }

    float rT = 1.f / (dT + 1e-16f);
    float rS = 1.f / (dS + 1e-16f);

    float4* row = (float4*)(out + (size_t)n * 256);
    float4 sk = row[lane];        // skip+bias (written once by node)
    float4 v1, v2;
    v1.x = sk.x + aS.x * rS; v1.y = sk.y + aS.y * rS;
    v1.z = sk.z + aS.z * rS; v1.w = sk.w + aS.w * rS;
    v2.x = sk.x + aT.x * rT; v2.y = sk.y + aT.y * rT;
    v2.z = sk.z + aT.z * rT; v2.w = sk.w + aT.w * rT;

    // LayerNorm over 256 within the warp
    float s = v1.x + v1.y + v1.z + v1.w + v2.x + v2.y + v2.z + v2.w;
    #pragma unroll
    for (int off = 16; off; off >>= 1) s += __shfl_xor_sync(0xffffffffu, s, off);
    float mu = s * (1.f / 256.f);
    float dx, sq = 0.f;
    dx = v1.x - mu; sq += dx * dx;  dx = v1.y - mu; sq += dx * dx;
    dx = v1.z - mu; sq += dx * dx;  dx = v1.w - mu; sq += dx * dx;
    dx = v2.x - mu; sq += dx * dx;  dx = v2.y - mu; sq += dx * dx;
    dx = v2.z - mu; sq += dx * dx;  dx = v2.w - mu; sq += dx * dx;
    #pragma unroll
    for (int off = 16; off; off >>= 1) sq += __shfl_xor_sync(0xffffffffu, sq, off);
    float inv = rsqrtf(sq * (1.f / 256.f) + 1e-5f);
    float4 g1 = ((const float4*)gamma)[lane], g2 = ((const float4*)gamma)[32 + lane];
    float4 b1 = ((const float4*)beta)[lane],  b2 = ((const float4*)beta)[32 + lane];
    v1.x = (v1.x - mu) * inv * g1.x + b1.x;  v1.y = (v1.y - mu) * inv * g1.y + b1.y;
    v1.z = (v1.z - mu) * inv * g1.z + b1.z;  v1.w = (v1.w - mu) * inv * g1.w + b1.w;
    v2.x = (v2.x - mu) * inv * g2.x + b2.x;  v2.y = (v2.y - mu) * inv * g2.y + b2.y;
    v2.z = (v2.z - mu) * inv * g2.z + b2.z;  v2.w = (v2.w - mu) * inv * g2.w + b2.w;
    row[lane] = v1;
    row[32 + lane] = v2;
}

// ---------------- launch ---------------------------------------------------
extern "C" void kernel_launch(void* const* d_in, const int* in_sizes, int n_in,
                              void* d_out, int out_size) {
    int o = (in_sizes[5] == 1) ? 0 : -1;
    const float* x     = (const float*)d_in[0];
    const int*   eidx  = (const int*)  d_in[1];
    const float* edges = (const float*)d_in[2];
    const float* ins   = (const float*)d_in[3];
    const int*   bids  = (const int*)  d_in[4];
    const float* Wp    = (const float*)d_in[6 + o];
    const float* We    = (const float*)d_in[7 + o];
    const float* Wsi   = (const float*)d_in[8 + o];
    const float* bsi   = (const float*)d_in[9 + o];
    const float* Wti   = (const float*)d_in[10 + o];
    const float* bti   = (const float*)d_in[11 + o];
    const float* Wei   = (const float*)d_in[12 + o];
    const float* bei   = (const float*)d_in[13 + o];
    const float* asrc  = (const float*)d_in[14 + o];
    const float* atrg  = (const float*)d_in[15 + o];
    const float* aedge = (const float*)d_in[16 + o];
    const float* bias  = (const float*)d_in[17 + o];
    const float* Wsk   = (const float*)d_in[18 + o];
    const float* gam   = (const float*)d_in[19 + o];
    const float* bet   = (const float*)d_in[20 + o];
    float* out = (float*)d_out;

    cudaFuncSetAttribute(node_kernel, cudaFuncAttributeMaxDynamicSharedMemorySize, SMEM_BYTES);

    zero_kernel<<<(NN / 4 + 255) / 256, 256>>>();
    prep_kernel<<<BB, 128>>>(ins, Wsi, bsi, Wti, bti, Wei, bei, asrc, atrg, aedge, We);
    node_kernel<<<NN / TILE_N, NTHR, SMEM_BYTES>>>(x, Wp, Wsk, bias, out);
    escore_kernel<<<888, 256>>>(eidx, edges, bids);
    gather_kernel<<<NN / 8, 256>>>(gam, bet, out);
}

// round 15
// speedup vs baseline: 1.3437x; 1.0362x over previous
#include <cuda_runtime.h>
#include <cuda_fp16.h>

#define HH   4
#define FF   32
#define HFD  128          // H*F
#define FIN  128
#define EDIM 64
#define HID  256
#define BB   64
#define MLE  1500
#define NN   (BB*MLE)     // 96000
#define EE   600000
#define CAP  64           // per-node incidence capacity (P(overflow) ~ 1e-50)

typedef unsigned long long u64;

// ---------------- scratch (device globals; no allocation allowed) ----------
__device__ __half g_proj[NN*HFD];     // 24.6 MB (fp16: L2-resident for gather)
__device__ float g_ss[NN*HH];
__device__ float g_st[NN*HH];
__device__ float g_usrc[BB*HFD];
__device__ float g_utrg[BB*HFD];
__device__ float g_v[BB*HH*EDIM];
__device__ unsigned g_max_ord;
__device__ int    g_degt[NN];
__device__ int    g_degs[NN];
__device__ int    g_nbrt[NN*CAP];     // src endpoint of edges whose trg == n
__device__ int    g_nbrs[NN*CAP];     // trg endpoint of edges whose src == n
__device__ float4 g_sct[NN*CAP];      // raw score4 of those edges
__device__ float4 g_scs[NN*CAP];      // raw score4

// ---------------- helpers --------------------------------------------------
__device__ __forceinline__ unsigned f2ord(float f) {
    unsigned b = __float_as_uint(f);
    return (b & 0x80000000u) ? ~b : (b | 0x80000000u);
}
__device__ __forceinline__ float ord2f(unsigned u) {
    unsigned b = (u & 0x80000000u) ? (u & 0x7fffffffu) : ~u;
    return __uint_as_float(b);
}
__device__ __forceinline__ float lrelu(float x) { return x > 0.f ? x : 0.2f * x; }
__device__ __forceinline__ float comp4(float4 v, int h) {
    return h == 0 ? v.x : h == 1 ? v.y : h == 2 ? v.z : v.w;
}
// packed f32x2 (sm_103a FFMA2 — only reachable via PTX)
__device__ __forceinline__ u64 pack2(float lo, float hi) {
    u64 r; asm("mov.b64 %0, {%1, %2};" : "=l"(r) : "f"(lo), "f"(hi)); return r;
}
__device__ __forceinline__ void unpack2(u64 v, float& lo, float& hi) {
    asm("mov.b64 {%0, %1}, %2;" : "=f"(lo), "=f"(hi) : "l"(v));
}
__device__ __forceinline__ u64 fma2(u64 a, u64 b, u64 c) {
    u64 d; asm("fma.rn.f32x2 %0, %1, %2, %3;" : "=l"(d) : "l"(a), "l"(b), "l"(c)); return d;
}

// ---------------- K0: zero degree counters + init max ----------------------
__global__ void zero_kernel() {
    int i = blockIdx.x * 256 + threadIdx.x;
    if (i < NN / 4) {
        ((int4*)g_degt)[i] = make_int4(0, 0, 0, 0);
        ((int4*)g_degs)[i] = make_int4(0, 0, 0, 0);
    }
    if (i == 0) g_max_ord = 0x007FFFFFu;   // encodes -inf
}

// ---------------- K1: per-batch instruction bridges ------------------------
__global__ void prep_kernel(const float* __restrict__ ins,
                            const float* __restrict__ Wsi, const float* __restrict__ bsi,
                            const float* __restrict__ Wti, const float* __restrict__ bti,
                            const float* __restrict__ Wei, const float* __restrict__ bei,
                            const float* __restrict__ asrc, const float* __restrict__ atrg,
                            const float* __restrict__ aedge, const float* __restrict__ Wedge) {
    __shared__ float si[HID];
    __shared__ float ce[HFD];
    int b = blockIdx.x, t = threadIdx.x;   // 128 threads
    for (int k = t; k < HID; k += 128) si[k] = ins[b * HID + k];
    __syncthreads();
    float s1 = bsi[t], s2 = bti[t], s3 = bei[t];
    for (int k = 0; k < HID; k++) {
        float iv = si[k];
        s1 += iv * Wsi[k * HFD + t];
        s2 += iv * Wti[k * HFD + t];
        s3 += iv * Wei[k * HFD + t];
    }
    g_usrc[b * HFD + t] = s1 * asrc[t];
    g_utrg[b * HFD + t] = s2 * atrg[t];
    ce[t] = s3 * aedge[t];
    __syncthreads();
    for (int o = t; o < HH * EDIM; o += 128) {
        int h = o >> 6, d = o & 63;
        float v = 0.f;
        #pragma unroll
        for (int f = 0; f < FF; f++) v += Wedge[d * HFD + h * FF + f] * ce[h * FF + f];
        g_v[b * HH * EDIM + o] = v;
    }
}

// ---------------- K2: fused node GEMM (FFMA2) + scores + skip init ---------
#define TILE_N 128
#define NTHR   512
#define KCOLS  256
#define XPAD   132
#define SMEM_BYTES ((FIN*KCOLS + TILE_N*XPAD) * 4)

__global__ void __launch_bounds__(NTHR, 1)
node_kernel(const float* __restrict__ x,
            const float* __restrict__ Wp,
            const float* __restrict__ Wsk,
            const float* __restrict__ bias,
            float* __restrict__ out) {
    extern __shared__ float smem[];
    float* sW = smem;                 // [128][256]
    float* sX = smem + FIN * KCOLS;   // [128][132] padded (reused as proj tile)
    int tid = threadIdx.x;

    const float4* Wp4 = (const float4*)Wp;
    const float4* Ws4 = (const float4*)Wsk;
    for (int i4 = tid; i4 < FIN * KCOLS / 4; i4 += NTHR) {
        int k = i4 >> 6, c4 = i4 & 63;
        float4 v = (c4 < 32) ? Wp4[k * 32 + c4] : Ws4[k * 32 + (c4 - 32)];
        ((float4*)sW)[i4] = v;
    }
    int base = blockIdx.x * TILE_N;
    const float4* x4 = (const float4*)x;
    for (int i = tid; i < TILE_N * 32; i += NTHR) {
        int r = i >> 5, k4 = i & 31;
        float4 v = x4[(base + r) * 32 + k4];
        *(float4*)&sX[r * XPAD + k4 * 4] = v;
    }
    __syncthreads();

    int tcol = tid & 31, trow = tid >> 5;   // 16 warps x 8 rows = 128 rows
    u64 acc2[8][4];
    #pragma unroll
    for (int j = 0; j < 8; j++)
        #pragma unroll
        for (int i = 0; i < 4; i++) acc2[j][i] = 0ull;

    for (int kk = 0; kk < FIN; kk += 4) {
        float4 xv4[8];
        #pragma unroll
        for (int j = 0; j < 8; j++)
            xv4[j] = *(const float4*)&sX[(trow * 8 + j) * XPAD + kk];  // broadcast
        #pragma unroll
        for (int q = 0; q < 4; q++) {
            int k = kk + q;
            u64 wr2[4];
            #pragma unroll
            for (int i = 0; i < 4; i++)
                wr2[i] = *(const u64*)&sW[k * KCOLS + 2 * (tcol + 32 * i)];
            #pragma unroll
            for (int j = 0; j < 8; j++) {
                float xv = (q == 0) ? xv4[j].x : (q == 1) ? xv4[j].y
                          : (q == 2) ? xv4[j].z : xv4[j].w;
                u64 x2 = pack2(xv, xv);
                #pragma unroll
                for (int i = 0; i < 4; i++) acc2[j][i] = fma2(x2, wr2[i], acc2[j][i]);
            }
        }
    }
    __syncthreads();

    #pragma unroll
    for (int j = 0; j < 8; j++) {
        int ln = trow * 8 + j;
        int gn = base + ln;
        #pragma unroll
        for (int i = 0; i < 4; i++) {
            int c0 = 2 * (tcol + 32 * i);
            float lo, hi; unpack2(acc2[j][i], lo, hi);
            if (i < 2) {
                *(__half2*)&g_proj[gn * HFD + c0] = __floats2half2_rn(lo, hi);
                sX[ln * XPAD + c0] = lo;
                sX[ln * XPAD + c0 + 1] = hi;
            } else {
                int oj = c0 - HFD;
                out[(size_t)gn * 256 + oj] = lo + bias[oj];         // first half only
                out[(size_t)gn * 256 + oj + 1] = hi + bias[oj + 1];
            }
        }
    }
    __syncthreads();

    int ln = tid & 127, h = tid >> 7;       // 512 threads = 128 nodes x 4 heads
    int gn = base + ln;
    int b = gn / MLE;
    const float* us = g_usrc + b * HFD + h * FF;
    const float* ut = g_utrg + b * HFD + h * FF;
    const float* pr = sX + ln * XPAD + h * FF;
    float a = 0.f, c2 = 0.f;
    #pragma unroll
    for (int f = 0; f < FF; f++) { float p = pr[f]; a = fmaf(p, us[f], a); c2 = fmaf(p, ut[f], c2); }
    g_ss[gn * HH + h] = a;
    g_st[gn * HH + h] = c2;
}

// ---------------- K3: per-edge scores (8 lanes/edge) + packed lists --------
__global__ void escore_kernel(const int* __restrict__ eidx,
                              const float* __restrict__ edges,
                              const int* __restrict__ bids) {
    int gwarp = (blockIdx.x * 256 + threadIdx.x) >> 5;
    int nwarps = gridDim.x * 8;
    int lane = threadIdx.x & 31;
    int g = lane >> 3, l = lane & 7;
    const float4* v4 = (const float4*)g_v;

    float m = -3.4e38f;
    for (int grp = gwarp; grp < EE / 4; grp += nwarps) {
        int e = grp * 4 + g;
        int b = __ldg(bids + e);
        const float4* er = (const float4*)edges + e * 16;
        float4 ea = er[l];        // chunk l      (line 0 of row)
        float4 eb = er[8 + l];    // chunk 8+l    (line 1 of row)
        const float4* vb = v4 + b * 64;
        float se[HH];
        #pragma unroll
        for (int h = 0; h < HH; h++) {
            float4 va = __ldg(vb + h * 16 + l);       // 1 line/group
            float4 vc = __ldg(vb + h * 16 + 8 + l);   // 1 line/group
            se[h] = ea.x * va.x + ea.y * va.y + ea.z * va.z + ea.w * va.w
                  + eb.x * vc.x + eb.y * vc.y + eb.z * vc.z + eb.w * vc.w;
        }
        #pragma unroll
        for (int off = 1; off < 8; off <<= 1) {
            se[0] += __shfl_xor_sync(0xffffffffu, se[0], off);
            se[1] += __shfl_xor_sync(0xffffffffu, se[1], off);
            se[2] += __shfl_xor_sync(0xffffffffu, se[2], off);
            se[3] += __shfl_xor_sync(0xffffffffu, se[3], off);
        }
        if (l < 2) {
            int src = __ldg(eidx + e), trg = __ldg(eidx + EE + e);
            float4 ss = __ldg((const float4*)g_ss + src);   // same addr both lanes
            float4 st = __ldg((const float4*)g_st + trg);
            float s0 = lrelu(ss.x + st.x + se[0]);
            float s1 = lrelu(ss.y + st.y + se[1]);
            float s2 = lrelu(ss.z + st.z + se[2]);
            float s3 = lrelu(ss.w + st.w + se[3]);
            if (l == 0) {
                m = fmaxf(m, fmaxf(fmaxf(s0, s1), fmaxf(s2, s3)));
                int pt = atomicAdd(&g_degt[trg], 1);
                if (pt < CAP) {
                    g_nbrt[trg * CAP + pt] = src;
                    g_sct[trg * CAP + pt] = make_float4(s0, s1, s2, s3);
                }
            } else {
                int ps = atomicAdd(&g_degs[src], 1);
                if (ps < CAP) {
                    g_nbrs[src * CAP + ps] = trg;
                    g_scs[src * CAP + ps] = make_float4(s0, s1, s2, s3);
                }
            }
        }
    }
    #pragma unroll
    for (int off = 16; off; off >>= 1) m = fmaxf(m, __shfl_xor_sync(0xffffffffu, m, off));
    __shared__ float wm[8];
    if ((threadIdx.x & 31) == 0) wm[threadIdx.x >> 5] = m;
    __syncthreads();
    if (threadIdx.x < 8) {
        m = wm[threadIdx.x];
        #pragma unroll
        for (int off = 4; off; off >>= 1) m = fmaxf(m, __shfl_xor_sync(0xffu, m, off));
        if (threadIdx.x == 0) atomicMax(&g_max_ord, f2ord(m));
    }
}

// ---------------- K4: gather: exp + denom + aggregate + skip + LayerNorm ---
// proj rows read as fp16 (8B/lane), converted to fp32 for accumulation.
__global__ void gather_kernel(const float* __restrict__ gamma,
                              const float* __restrict__ beta,
                              float* __restrict__ out) {
    __shared__ int   s_nbr[2][8][32];
    __shared__ float s_ex [2][8][32][4];
    int w = threadIdx.x >> 5;
    int n = blockIdx.x * 8 + w;
    int lane = threadIdx.x & 31;
    int h = lane >> 3;
    float M = ord2f(g_max_ord);
    int dt = g_degt[n]; if (dt > CAP) dt = CAP;
    int ds = g_degs[n]; if (ds > CAP) ds = CAP;
    int m32t = dt < 32 ? dt : 32;
    int m32s = ds < 32 ? ds : 32;
    const uint2* pr2 = (const uint2*)g_proj;   // 32 uint2 per 128-half row

    if (lane < m32t) {
        s_nbr[0][w][lane] = __ldg(g_nbrt + n * CAP + lane);     // coalesced
        float4 sc = __ldg(g_sct + n * CAP + lane);              // coalesced
        s_ex[0][w][lane][0] = __expf(sc.x - M);
        s_ex[0][w][lane][1] = __expf(sc.y - M);
        s_ex[0][w][lane][2] = __expf(sc.z - M);
        s_ex[0][w][lane][3] = __expf(sc.w - M);
    }
    if (lane < m32s) {
        s_nbr[1][w][lane] = __ldg(g_nbrs + n * CAP + lane);
        float4 sc = __ldg(g_scs + n * CAP + lane);
        s_ex[1][w][lane][0] = __expf(sc.x - M);
        s_ex[1][w][lane][1] = __expf(sc.y - M);
        s_ex[1][w][lane][2] = __expf(sc.z - M);
        s_ex[1][w][lane][3] = __expf(sc.w - M);
    }
    __syncwarp();

    float dT = 0.f, dS = 0.f;
    float4 aT = make_float4(0.f, 0.f, 0.f, 0.f);
    float4 aS = make_float4(0.f, 0.f, 0.f, 0.f);
    int mmax = m32t > m32s ? m32t : m32s;
    for (int it = 0; it < mmax; it += 4) {
        #pragma unroll
        for (int j = 0; j < 4; j++) {
            int idx = it + j;
            if (idx < m32t) {
                int nbr = s_nbr[0][w][idx];           // broadcast LDS
                float a = s_ex[0][w][idx][h];         // 4-way broadcast LDS
                uint2 u = __ldg(pr2 + nbr * 32 + lane);
                float2 p01 = __half22float2(*(__half2*)&u.x);
                float2 p23 = __half22float2(*(__half2*)&u.y);
                dT += a;
                aT.x += p01.x * a; aT.y += p01.y * a; aT.z += p23.x * a; aT.w += p23.y * a;
            }
            if (idx < m32s) {
                int nbr = s_nbr[1][w][idx];
                float a = s_ex[1][w][idx][h];
                uint2 u = __ldg(pr2 + nbr * 32 + lane);
                float2 p01 = __half22float2(*(__half2*)&u.x);
                float2 p23 = __half22float2(*(__half2*)&u.y);
                dS += a;
                aS.x += p01.x * a; aS.y += p01.y * a; aS.z += p23.x * a; aS.w += p23.y * a;
            }
        }
    }
    // rare tails (deg > 32)
    for (int it = 32; it < dt; it++) {
        int nbr = g_nbrt[n * CAP + it];
        float a = __expf(comp4(g_sct[n * CAP + it], h) - M);
        uint2 u = __ldg(pr2 + nbr * 32 + lane);
        float2 p01 = __half22float2(*(__half2*)&u.x);
        float2 p23 = __half22float2(*(__half2*)&u.y);
        dT += a;
        aT.x += p01.x * a; aT.y += p01.y * a; aT.z += p23.x * a; aT.w += p23.y * a;
    }
    for (int it = 32; it < ds; it++) {
        int nbr = g_nbrs[n * CAP + it];
        float a = __expf(comp4(g_scs[n * CAP + it], h) - M);
        uint2 u = __ldg(pr2 + nbr * 32 + lane);
        float2 p01 = __half22float2(*(__half2*)&u.x);
        float2 p23 = __half22float2(*(__half2*)&u.y);
        dS += a;
        aS.x += p01.x * a; aS.y += p01.y * a; aS.z += p23.x * a; aS.w += p23.y * a;
    }

    float rT = 1.f / (dT + 1e-16f);
    float rS = 1.f / (dS + 1e-16f);

    float4* row = (float4*)(out + (size_t)n * 256);
    float4 sk = row[lane];        // skip+bias (written once by node)
    float4 v1, v2;
    v1.x = sk.x + aS.x * rS; v1.y = sk.y + aS.y * rS;
    v1.z = sk.z + aS.z * rS; v1.w = sk.w + aS.w * rS;
    v2.x = sk.x + aT.x * rT; v2.y = sk.y + aT.y * rT;
    v2.z = sk.z + aT.z * rT; v2.w = sk.w + aT.w * rT;

    // LayerNorm over 256 within the warp
    float s = v1.x + v1.y + v1.z + v1.w + v2.x + v2.y + v2.z + v2.w;
    #pragma unroll
    for (int off = 16; off; off >>= 1) s += __shfl_xor_sync(0xffffffffu, s, off);
    float mu = s * (1.f / 256.f);
    float dx, sq = 0.f;
    dx = v1.x - mu; sq += dx * dx;  dx = v1.y - mu; sq += dx * dx;
    dx = v1.z - mu; sq += dx * dx;  dx = v1.w - mu; sq += dx * dx;
    dx = v2.x - mu; sq += dx * dx;  dx = v2.y - mu; sq += dx * dx;
    dx = v2.z - mu; sq += dx * dx;  dx = v2.w - mu; sq += dx * dx;
    #pragma unroll
    for (int off = 16; off; off >>= 1) sq += __shfl_xor_sync(0xffffffffu, sq, off);
    float inv = rsqrtf(sq * (1.f / 256.f) + 1e-5f);
    float4 g1 = ((const float4*)gamma)[lane], g2 = ((const float4*)gamma)[32 + lane];
    float4 b1 = ((const float4*)beta)[lane],  b2 = ((const float4*)beta)[32 + lane];
    v1.x = (v1.x - mu) * inv * g1.x + b1.x;  v1.y = (v1.y - mu) * inv * g1.y + b1.y;
    v1.z = (v1.z - mu) * inv * g1.z + b1.z;  v1.w = (v1.w - mu) * inv * g1.w + b1.w;
    v2.x = (v2.x - mu) * inv * g2.x + b2.x;  v2.y = (v2.y - mu) * inv * g2.y + b2.y;
    v2.z = (v2.z - mu) * inv * g2.z + b2.z;  v2.w = (v2.w - mu) * inv * g2.w + b2.w;
    row[lane] = v1;
    row[32 + lane] = v2;
}

// ---------------- launch ---------------------------------------------------
extern "C" void kernel_launch(void* const* d_in, const int* in_sizes, int n_in,
                              void* d_out, int out_size) {
    int o = (in_sizes[5] == 1) ? 0 : -1;
    const float* x     = (const float*)d_in[0];
    const int*   eidx  = (const int*)  d_in[1];
    const float* edges = (const float*)d_in[2];
    const float* ins   = (const float*)d_in[3];
    const int*   bids  = (const int*)  d_in[4];
    const float* Wp    = (const float*)d_in[6 + o];
    const float* We    = (const float*)d_in[7 + o];
    const float* Wsi   = (const float*)d_in[8 + o];
    const float* bsi   = (const float*)d_in[9 + o];
    const float* Wti   = (const float*)d_in[10 + o];
    const float* bti   = (const float*)d_in[11 + o];
    const float* Wei   = (const float*)d_in[12 + o];
    const float* bei   = (const float*)d_in[13 + o];
    const float* asrc  = (const float*)d_in[14 + o];
    const float* atrg  = (const float*)d_in[15 + o];
    const float* aedge = (const float*)d_in[16 + o];
    const float* bias  = (const float*)d_in[17 + o];
    const float* Wsk   = (const float*)d_in[18 + o];
    const float* gam   = (const float*)d_in[19 + o];
    const float* bet   = (const float*)d_in[20 + o];
    float* out = (float*)d_out;

    cudaFuncSetAttribute(node_kernel, cudaFuncAttributeMaxDynamicSharedMemorySize, SMEM_BYTES);

    zero_kernel<<<(NN / 4 + 255) / 256, 256>>>();
    prep_kernel<<<BB, 128>>>(ins, Wsi, bsi, Wti, bti, Wei, bei, asrc, atrg, aedge, We);
    node_kernel<<<NN / TILE_N, NTHR, SMEM_BYTES>>>(x, Wp, Wsk, bias, out);
    escore_kernel<<<888, 256>>>(eidx, edges, bids);
    gather_kernel<<<NN / 8, 256>>>(gam, bet, out);
}